// round 12
// baseline (speedup 1.0000x reference)
#include <cuda_runtime.h>
#include <cuda_fp16.h>
#include <cstdint>
#include <math.h>

#define BATCH 4
#define SEQ   4096
#define DIM   1024
#define NH    16
#define HD    64
#define BH    (BATCH*NH)          // 64
#define MTOT  (BATCH*SEQ)         // 16384
#define LNEPS 1e-5f
#define KS4   4                   // kkt2 i-splits

// ---------------- scratch (static device globals; no allocation) -------------
__device__ __align__(16) __half g_xh [(size_t)MTOT*DIM];
__device__ __align__(16) __half g_xt [(size_t)BATCH*DIM*SEQ];   // X^T per batch
__device__ __align__(16) __half g_wh [4][(size_t)DIM*DIM];
__device__ __align__(16) float  g_gp [(size_t)BATCH*2*DIM*DIM]; // G split-K partials
__device__ __align__(16) __half g_gm [(size_t)BATCH*DIM*DIM];   // G = X^T X
__device__ __align__(16) __half g_hk [(size_t)BATCH*DIM*DIM];   // Hk = Wk G
__device__ __align__(16) __half g_wp [(size_t)BATCH*DIM*DIM];   // folded W'
__device__ __align__(16) __half g_w2 [(size_t)BATCH*DIM*DIM];   // folded W2^T
__device__ __align__(16) __half g_projh[(size_t)MTOT*DIM];
__device__ float g_part[KS4*BH*2*HD*HD];
__device__ float g_amap[BH*HD*HD];

// ---------------- async copy / mma helpers ------------------------------------
#define CP16(dst_u32, src_ptr) \
    asm volatile("cp.async.cg.shared.global [%0], [%1], 16;\n" \
                 :: "r"(dst_u32), "l"(src_ptr))
#define CPCOMMIT() asm volatile("cp.async.commit_group;\n" ::: "memory")
#define CPWAIT1()  asm volatile("cp.async.wait_group 1;\n" ::: "memory")
#define CPWAIT0()  asm volatile("cp.async.wait_group 0;\n" ::: "memory")

__device__ __forceinline__ void ldsm4(unsigned r[4], unsigned addr) {
    asm volatile("ldmatrix.sync.aligned.m8n8.x4.shared.b16 {%0,%1,%2,%3}, [%4];"
                 : "=r"(r[0]), "=r"(r[1]), "=r"(r[2]), "=r"(r[3]) : "r"(addr));
}

__device__ __forceinline__ void mma16816(float* c, const unsigned a[4],
                                         unsigned b0, unsigned b1) {
    asm volatile(
        "mma.sync.aligned.m16n8k16.row.col.f32.f16.f16.f32 "
        "{%0,%1,%2,%3}, {%4,%5,%6,%7}, {%8,%9}, {%0,%1,%2,%3};"
        : "+f"(c[0]), "+f"(c[1]), "+f"(c[2]), "+f"(c[3])
        : "r"(a[0]), "r"(a[1]), "r"(a[2]), "r"(a[3]), "r"(b0), "r"(b1));
}

// ---------------- f32 -> fp16: all 4 weights in one launch ---------------------
__global__ __launch_bounds__(256) void convw_kernel(
    const float* __restrict__ w0, const float* __restrict__ w1,
    const float* __restrict__ w2, const float* __restrict__ w3)
{
    const float* srcs[4] = { w0, w1, w2, w3 };
    const float* src = srcs[blockIdx.y];
    __half* dst = &g_wh[blockIdx.y][0];
    size_t base = (size_t)(blockIdx.x * blockDim.x + threadIdx.x) * 8;
    float4 v0 = *(const float4*)(src + base);
    float4 v1 = *(const float4*)(src + base + 4);
    __half o[8];
    o[0] = __float2half_rn(v0.x); o[1] = __float2half_rn(v0.y);
    o[2] = __float2half_rn(v0.z); o[3] = __float2half_rn(v0.w);
    o[4] = __float2half_rn(v1.x); o[5] = __float2half_rn(v1.y);
    o[6] = __float2half_rn(v1.z); o[7] = __float2half_rn(v1.w);
    *(uint4*)(dst + base) = *(const uint4*)o;
}

// ---------- fused x(f32) -> xh(fp16 row-major) + xt(fp16 transposed) ----------
__global__ __launch_bounds__(256) void convx_kernel(const float* __restrict__ x)
{
    int ib = blockIdx.x, nb = blockIdx.y, b = blockIdx.z;
    __shared__ __half Ts[64][64];
    int tid = threadIdx.x;
    const float* src = x + ((size_t)(b * SEQ + nb * 64)) * DIM + ib * 64;
    __half* xh = g_xh + ((size_t)(b * SEQ + nb * 64)) * DIM + ib * 64;
#pragma unroll
    for (int it = 0; it < 2; ++it) {
        int idx = tid + it * 256;
        int r  = idx >> 3;
        int cc = idx & 7;
        float4 v0 = *(const float4*)(src + (size_t)r * DIM + cc * 8);
        float4 v1 = *(const float4*)(src + (size_t)r * DIM + cc * 8 + 4);
        __half o[8];
        o[0] = __float2half_rn(v0.x); o[1] = __float2half_rn(v0.y);
        o[2] = __float2half_rn(v0.z); o[3] = __float2half_rn(v0.w);
        o[4] = __float2half_rn(v1.x); o[5] = __float2half_rn(v1.y);
        o[6] = __float2half_rn(v1.z); o[7] = __float2half_rn(v1.w);
        *(uint4*)(xh + (size_t)r * DIM + cc * 8) = *(const uint4*)o;
        int ccs = cc ^ ((r >> 3) & 7);
        *(uint4*)&Ts[r][ccs * 8] = *(const uint4*)o;
    }
    __syncthreads();
    __half* dst = g_xt + ((size_t)b * DIM + ib * 64) * SEQ + nb * 64;
#pragma unroll
    for (int it = 0; it < 2; ++it) {
        int idx = tid + it * 256;
        int ng = idx & 7;
        int i  = idx >> 3;
        __half o[8];
#pragma unroll
        for (int k = 0; k < 8; ++k) {
            int n = ng * 8 + k;
            int cc = (i >> 3) ^ ((n >> 3) & 7);
            o[k] = Ts[n][cc * 8 + (i & 7)];
        }
        *(uint4*)(dst + (size_t)i * SEQ + ng * 8) = *(const uint4*)o;
    }
}

// ------------- G split-K GEMM: triangle tiles, f32 partial out ----------------
// 2-stage double buffer, 64KB smem, 3 CTAs/SM.
__global__ __launch_bounds__(256, 3) void gsplit_kernel()
{
    extern __shared__ __half sm[];
    const unsigned smem_base = (unsigned)__cvta_generic_to_shared(sm);
    const int tid  = threadIdx.x;
    const int lane = tid & 31;
    const int warp = tid >> 5;
    const int wm = (warp >> 2) * 64;
    const int wn = (warp & 3) * 32;
    const int bm = blockIdx.y * 128;
    const int bn = blockIdx.x * 128;
    if (bn > bm) return;
    const int b = blockIdx.z >> 1;
    const int sp = blockIdx.z & 1;
    const int g4 = lane >> 2;
    const int tg = lane & 3;

    const __half* A2 = g_xt + (size_t)b * DIM * SEQ;
    float* Cf = g_gp + (size_t)blockIdx.z * DIM * DIM;

    float acc[4][4][4];
#pragma unroll
    for (int t = 0; t < 4; ++t)
#pragma unroll
        for (int u = 0; u < 4; ++u)
#pragma unroll
            for (int r = 0; r < 4; ++r) acc[t][u][r] = 0.0f;

    auto load_chunk = [&](int kc, int bf) {
#pragma unroll
        for (int it = 0; it < 4; ++it) {
            int idx = tid + it * 256;
            int row = idx >> 3;
            int c8  = idx & 7;
            const __half* sa = A2 + (size_t)(bm + row) * SEQ + kc * 64 + c8 * 8;
            const __half* sb = A2 + (size_t)(bn + row) * SEQ + kc * 64 + c8 * 8;
            unsigned sw = (unsigned)((c8 ^ (row & 7)) * 16);
            CP16(smem_base + bf * 16384 + row * 128 + sw, sa);
            CP16(smem_base + 32768 + bf * 16384 + row * 128 + sw, sb);
        }
    };

    const int khalf = lane >> 4;
    int rowA[4], rowB[2];
#pragma unroll
    for (int t = 0; t < 4; ++t) rowA[t] = wm + t * 16 + (lane & 15);
#pragma unroll
    for (int p = 0; p < 2; ++p) rowB[p] = wn + p * 16 + (lane & 15);

    const int k0 = sp * 32;
    load_chunk(k0, 0); CPCOMMIT();

    for (int kc = 0; kc < 32; ++kc) {
        __syncthreads();   // prior compute on buffer (kc+1)&1 done
        if (kc + 1 < 32) { load_chunk(k0 + kc + 1, (kc + 1) & 1); CPCOMMIT(); CPWAIT1(); }
        else             { CPWAIT0(); }
        __syncthreads();

        const int bf = kc & 1;
        const unsigned abase = smem_base + bf * 16384;
        const unsigned bbase = smem_base + 32768 + bf * 16384;

#pragma unroll
        for (int s = 0; s < 4; ++s) {
            const int ch = s * 2 + khalf;
            unsigned a[4][4], bfr[2][4];
#pragma unroll
            for (int t = 0; t < 4; ++t)
                ldsm4(a[t], abase + rowA[t] * 128 +
                             (unsigned)((ch ^ (rowA[t] & 7)) * 16));
#pragma unroll
            for (int p = 0; p < 2; ++p)
                ldsm4(bfr[p], bbase + rowB[p] * 128 +
                              (unsigned)((ch ^ (rowB[p] & 7)) * 16));
#pragma unroll
            for (int t = 0; t < 4; ++t)
#pragma unroll
                for (int u = 0; u < 4; ++u) {
                    int p = u >> 1, h = u & 1;
                    mma16816(acc[t][u], a[t], bfr[p][h], bfr[p][2 + h]);
                }
        }
    }

#pragma unroll
    for (int t = 0; t < 4; ++t) {
        int r = bm + wm + t * 16 + g4;
#pragma unroll
        for (int u = 0; u < 4; ++u) {
            int c = bn + wn + u * 8 + tg * 2;
            *(float2*)&Cf[(size_t)r * DIM + c] =
                make_float2(acc[t][u][0], acc[t][u][1]);
            *(float2*)&Cf[(size_t)(r + 8) * DIM + c] =
                make_float2(acc[t][u][2], acc[t][u][3]);
        }
    }
}

// ------------- greduce: sum 2 partials -> fp16 G + symmetric mirror -----------
__global__ __launch_bounds__(256) void greduce_kernel()
{
    int bm = blockIdx.y * 128, bn = blockIdx.x * 128;
    if (bn > bm) return;
    int b = blockIdx.z;
    int tid = threadIdx.x;
    __shared__ __half S[128][132];

    const float* p0 = g_gp + (size_t)(b * 2 + 0) * DIM * DIM;
    const float* p1 = g_gp + (size_t)(b * 2 + 1) * DIM * DIM;
    __half* Gm = g_gm + (size_t)b * DIM * DIM;

#pragma unroll
    for (int it = 0; it < 16; ++it) {
        int idx = tid + it * 256;
        int r  = idx >> 5;
        int c4 = (idx & 31) * 4;
        size_t off = (size_t)(bm + r) * DIM + bn + c4;
        float4 a = *(const float4*)(p0 + off);
        float4 c = *(const float4*)(p1 + off);
        __half2 h0 = __floats2half2_rn(a.x + c.x, a.y + c.y);
        __half2 h1 = __floats2half2_rn(a.z + c.z, a.w + c.w);
        __half o[4];
        *(__half2*)&o[0] = h0;
        *(__half2*)&o[2] = h1;
        *(uint2*)&Gm[off] = *(const uint2*)o;
        *(__half2*)&S[r][c4]     = h0;
        *(__half2*)&S[r][c4 + 2] = h1;
    }

    if (bn < bm) {
        __syncthreads();
#pragma unroll
        for (int it = 0; it < 8; ++it) {
            int idx = tid + it * 256;
            int j  = idx >> 4;
            int i0 = (idx & 15) * 8;
            __half o[8];
#pragma unroll
            for (int k = 0; k < 8; ++k) o[k] = S[i0 + k][j];
            *(uint4*)&Gm[(size_t)(bn + j) * DIM + bm + i0] = *(const uint4*)o;
        }
    }
}

// ---------------- fp16 GEMM: C[m,n]=sum_k A[m,k]*B[n,k] (fp16 out) -----------
// 2-stage double buffer, 64KB smem, 3 CTAs/SM.
__global__ __launch_bounds__(256, 3) void gemm_f16(
    const __half* __restrict__ A0, const __half* __restrict__ B0,
    const float* __restrict__ bias, __half* __restrict__ Ch0, int N,
    int nck, int lda, int ldb, size_t strA, size_t strB, size_t strC)
{
    extern __shared__ __half sm[];
    const unsigned smem_base = (unsigned)__cvta_generic_to_shared(sm);
    const int tid  = threadIdx.x;
    const int lane = tid & 31;
    const int warp = tid >> 5;
    const int wm = (warp >> 2) * 64;
    const int wn = (warp & 3) * 32;
    const int bm = blockIdx.y * 128;
    const int bn = blockIdx.x * 128;
    const int z  = blockIdx.z;
    const int g4 = lane >> 2;
    const int tg = lane & 3;

    const __half* A2 = A0 + (size_t)z * strA;
    const __half* B2 = B0 + (size_t)z * strB;
    __half* Ch = Ch0 + (size_t)z * strC;

    float acc[4][4][4];
#pragma unroll
    for (int t = 0; t < 4; ++t)
#pragma unroll
        for (int u = 0; u < 4; ++u)
#pragma unroll
            for (int r = 0; r < 4; ++r) acc[t][u][r] = 0.0f;

    auto load_chunk = [&](int kc, int bf) {
#pragma unroll
        for (int it = 0; it < 4; ++it) {
            int idx = tid + it * 256;
            int row = idx >> 3;
            int c8  = idx & 7;
            const __half* sa = A2 + (size_t)(bm + row) * lda + kc * 64 + c8 * 8;
            const __half* sb = B2 + (size_t)(bn + row) * ldb + kc * 64 + c8 * 8;
            unsigned sw = (unsigned)((c8 ^ (row & 7)) * 16);
            CP16(smem_base + bf * 16384 + row * 128 + sw, sa);
            CP16(smem_base + 32768 + bf * 16384 + row * 128 + sw, sb);
        }
    };

    const int khalf = lane >> 4;
    int rowA[4], rowB[2];
#pragma unroll
    for (int t = 0; t < 4; ++t) rowA[t] = wm + t * 16 + (lane & 15);
#pragma unroll
    for (int p = 0; p < 2; ++p) rowB[p] = wn + p * 16 + (lane & 15);

    load_chunk(0, 0); CPCOMMIT();

    for (int kc = 0; kc < nck; ++kc) {
        __syncthreads();
        if (kc + 1 < nck) { load_chunk(kc + 1, (kc + 1) & 1); CPCOMMIT(); CPWAIT1(); }
        else              { CPWAIT0(); }
        __syncthreads();

        const int bf = kc & 1;
        const unsigned abase = smem_base + bf * 16384;
        const unsigned bbase = smem_base + 32768 + bf * 16384;

#pragma unroll
        for (int s = 0; s < 4; ++s) {
            const int ch = s * 2 + khalf;
            unsigned a[4][4], b[2][4];
#pragma unroll
            for (int t = 0; t < 4; ++t)
                ldsm4(a[t], abase + rowA[t] * 128 +
                             (unsigned)((ch ^ (rowA[t] & 7)) * 16));
#pragma unroll
            for (int p = 0; p < 2; ++p)
                ldsm4(b[p], bbase + rowB[p] * 128 +
                             (unsigned)((ch ^ (rowB[p] & 7)) * 16));
#pragma unroll
            for (int t = 0; t < 4; ++t)
#pragma unroll
                for (int u = 0; u < 4; ++u) {
                    int p = u >> 1, h = u & 1;
                    mma16816(acc[t][u], a[t], b[p][h], b[p][2 + h]);
                }
        }
    }

#pragma unroll
    for (int t = 0; t < 4; ++t) {
        int r = bm + wm + t * 16 + g4;
#pragma unroll
        for (int u = 0; u < 4; ++u) {
            int c = bn + wn + u * 8 + tg * 2;
            float b0 = 0.0f, b1 = 0.0f;
            if (bias) { b0 = bias[c]; b1 = bias[c + 1]; }
            *(__half2*)&Ch[(size_t)r * N + c] =
                __floats2half2_rn(acc[t][u][0] + b0, acc[t][u][1] + b1);
            *(__half2*)&Ch[(size_t)(r + 8) * N + c] =
                __floats2half2_rn(acc[t][u][2] + b0, acc[t][u][3] + b1);
        }
    }
}

// -------- kkt2: kk/kv partials from Hk_h · [Wk_h | Wv_h]^T, i-split -----------
__global__ __launch_bounds__(256) void kkt2_kernel()
{
    int bh = blockIdx.x;
    int sp = blockIdx.y;
    int b = bh >> 4, h = bh & 15;
    const __half* hk = g_hk    + (size_t)b * DIM * DIM + (size_t)(h * HD) * DIM;
    const __half* wk = g_wh[1] + (size_t)(h * HD) * DIM;
    const __half* wv = g_wh[2] + (size_t)(h * HD) * DIM;

    __shared__ __half Hs[64][72];
    __shared__ __half Ts[128][72];
    const unsigned hb = (unsigned)__cvta_generic_to_shared(&Hs[0][0]);
    const unsigned tb = (unsigned)__cvta_generic_to_shared(&Ts[0][0]);
    const int tid = threadIdx.x;
    const int lane = tid & 31;
    const int warp = tid >> 5;
    const int wm = (warp >> 2) * 32;
    const int wn = (warp & 3) * 32;
    const int g4 = lane >> 2;
    const int tg = lane & 3;

    float acc[2][4][4];
#pragma unroll
    for (int mt = 0; mt < 2; ++mt)
#pragma unroll
        for (int u = 0; u < 4; ++u)
#pragma unroll
            for (int r = 0; r < 4; ++r) acc[mt][u][r] = 0.0f;

    const int khalf = lane >> 4;
    int rowA[2], rowB[2];
#pragma unroll
    for (int mt = 0; mt < 2; ++mt) rowA[mt] = wm + mt * 16 + (lane & 15);
#pragma unroll
    for (int p = 0; p < 2; ++p) rowB[p] = wn + p * 16 + (lane & 15);

    for (int i0 = sp * 256; i0 < sp * 256 + 256; i0 += 64) {
        __syncthreads();
#pragma unroll
        for (int it = 0; it < 2; ++it) {
            int idx = tid + it * 256;
            int r = idx >> 3, c8 = (idx & 7) * 8;
            *(uint4*)&Hs[r][c8] = *(const uint4*)(hk + (size_t)r * DIM + i0 + c8);
        }
#pragma unroll
        for (int it = 0; it < 4; ++it) {
            int idx = tid + it * 256;
            int r = idx >> 3, c8 = (idx & 7) * 8;
            const __half* src = (r < 64 ? wk + (size_t)r * DIM
                                        : wv + (size_t)(r - 64) * DIM) + i0 + c8;
            *(uint4*)&Ts[r][c8] = *(const uint4*)src;
        }
        __syncthreads();

#pragma unroll
        for (int ks = 0; ks < 4; ++ks) {
            unsigned a[2][4], bfr[2][4];
            unsigned colb = (unsigned)(ks * 32 + khalf * 16);
#pragma unroll
            for (int mt = 0; mt < 2; ++mt)
                ldsm4(a[mt], hb + rowA[mt] * 144 + colb);
#pragma unroll
            for (int p = 0; p < 2; ++p)
                ldsm4(bfr[p], tb + rowB[p] * 144 + colb);
#pragma unroll
            for (int mt = 0; mt < 2; ++mt)
#pragma unroll
                for (int u = 0; u < 4; ++u) {
                    int p = u >> 1, hh = u & 1;
                    mma16816(acc[mt][u], a[mt], bfr[p][hh], bfr[p][2 + hh]);
                }
        }
    }

    float* pkk = g_part + (size_t)(sp * BH + bh) * 2 * 4096;
    float* pkv = pkk + 4096;
#pragma unroll
    for (int mt = 0; mt < 2; ++mt) {
        int d = wm + mt * 16 + g4;
#pragma unroll
        for (int u = 0; u < 4; ++u) {
            int j = wn + u * 8 + tg * 2;
            float* dst = (j < 64) ? (pkk + d * 64 + j) : (pkv + d * 64 + (j - 64));
            *(float2*)dst = make_float2(acc[mt][u][0], acc[mt][u][1]);
            float* dst2 = (j < 64) ? (pkk + (d + 8) * 64 + j)
                                   : (pkv + (d + 8) * 64 + (j - 64));
            *(float2*)dst2 = make_float2(acc[mt][u][2], acc[mt][u][3]);
        }
    }
}

// ------- reduce partials, solve (kk+aI) X = ktv, column softmax ---------------
__global__ __launch_bounds__(256) void solve_kernel(
    const float* __restrict__ alpha_p, const float* __restrict__ temp_p)
{
    int bh = blockIdx.x;
    __shared__ float A[64][65];
    __shared__ float X[64][65];
    int tid = threadIdx.x;

    for (int i = tid; i < 4096; i += 256) {
        float skk = 0.0f, skv = 0.0f;
#pragma unroll
        for (int s = 0; s < KS4; ++s) {
            const float* p = g_part + ((size_t)(s * BH + bh) * 2) * 4096;
            skk += p[i];
            skv += p[4096 + i];
        }
        A[i >> 6][i & 63] = skk;
        X[i >> 6][i & 63] = skv;
    }
    __syncthreads();
    if (tid < 64) A[tid][tid] += alpha_p[0];

    int r  = tid >> 2;
    int c0 = (tid & 3) * 16;
    for (int pp = 0; pp < 64; ++pp) {
        __syncthreads();
        float pinv = 1.0f / A[pp][pp];
        __syncthreads();
        if (tid < 64)      A[pp][tid]      *= pinv;
        else if (tid < 128) X[pp][tid - 64] *= pinv;
        __syncthreads();
        float f = (r != pp) ? A[r][pp] : 0.0f;
        __syncthreads();
        if (r != pp) {
#pragma unroll
            for (int c = 0; c < 16; ++c) {
                A[r][c0 + c] = fmaf(-f, A[pp][c0 + c], A[r][c0 + c]);
                X[r][c0 + c] = fmaf(-f, X[pp][c0 + c], X[r][c0 + c]);
            }
        }
    }
    __syncthreads();

    if (tid < 64) {
        float invt = 1.0f / temp_p[0];
        float mx = -1e30f;
        for (int d = 0; d < 64; ++d) mx = fmaxf(mx, X[d][tid] * invt);
        float s = 0.0f;
        for (int d = 0; d < 64; ++d) s += expf(X[d][tid] * invt - mx);
        float inv_s = 1.0f / s;
        for (int d = 0; d < 64; ++d)
            g_amap[(size_t)bh * 4096 + d * 64 + tid] =
                expf(X[d][tid] * invt - mx) * inv_s;
    }
}

// ---------- fold1: W'_b[din, h*64+j] = sum_e Wq[h*64+e, din] * amap[e, j] -----
__global__ __launch_bounds__(256) void fold1_kernel()
{
    int bh = blockIdx.x;
    int chunk = blockIdx.y;
    int b = bh >> 4, h = bh & 15;

    __shared__ __half WqS[64][256];
    __shared__ float  AmS[64][64];
    int tid = threadIdx.x;

    const __half* wq = g_wh[0] + (size_t)(h * 64) * DIM + chunk * 256;
#pragma unroll
    for (int it = 0; it < 8; ++it) {
        int idx = tid + it * 256;
        int e = idx >> 5;
        int c8 = (idx & 31) * 8;
        *(uint4*)&WqS[e][c8] = *(const uint4*)(wq + (size_t)e * DIM + c8);
    }
#pragma unroll
    for (int it = 0; it < 4; ++it) {
        int idx = tid + it * 256;
        int e = idx >> 4;
        int j4 = (idx & 15) * 4;
        *(float4*)&AmS[e][j4] =
            *(const float4*)&g_amap[(size_t)bh * 4096 + e * 64 + j4];
    }
    __syncthreads();

    int ty = tid >> 3;
    int tx = tid & 7;
    float acc[8][8];
#pragma unroll
    for (int i = 0; i < 8; ++i)
#pragma unroll
        for (int j = 0; j < 8; ++j) acc[i][j] = 0.0f;

#pragma unroll 4
    for (int e = 0; e < 64; ++e) {
        __half ah[8];
        *(uint4*)ah = *(const uint4*)&WqS[e][ty * 8];
        float bv[8];
        float4 b0 = *(const float4*)&AmS[e][tx * 8];
        float4 b1 = *(const float4*)&AmS[e][tx * 8 + 4];
        bv[0]=b0.x; bv[1]=b0.y; bv[2]=b0.z; bv[3]=b0.w;
        bv[4]=b1.x; bv[5]=b1.y; bv[6]=b1.z; bv[7]=b1.w;
#pragma unroll
        for (int i = 0; i < 8; ++i) {
            float av = __half2float(ah[i]);
#pragma unroll
            for (int j = 0; j < 8; ++j) acc[i][j] = fmaf(av, bv[j], acc[i][j]);
        }
    }

    __half* wp = g_wp + (size_t)b * DIM * DIM;
#pragma unroll
    for (int i = 0; i < 8; ++i) {
        int din = chunk * 256 + ty * 8 + i;
        __half o[8];
#pragma unroll
        for (int j = 0; j < 8; ++j) o[j] = __float2half_rn(acc[i][j]);
        *(uint4*)&wp[(size_t)din * DIM + h * 64 + tx * 8] = *(const uint4*)o;
    }
}

// ---------------- LayerNorm(proj(fp16) + x(f32)) ------------------------------
__global__ __launch_bounds__(256) void ln_kernel(
    const float* __restrict__ x, const float* __restrict__ gamma,
    const float* __restrict__ beta, float* __restrict__ out)
{
    int row = blockIdx.x;
    int tid = threadIdx.x;
    const __half* pr = g_projh + (size_t)row * DIM;
    const float*  xr = x       + (size_t)row * DIM;

    uint2 pu = *(const uint2*)(pr + tid * 4);
    __half2 p0 = *reinterpret_cast<__half2*>(&pu.x);
    __half2 p1 = *reinterpret_cast<__half2*>(&pu.y);
    float4 xv = *(const float4*)(xr + tid * 4);
    float v[4] = { __low2float(p0) + xv.x, __high2float(p0) + xv.y,
                   __low2float(p1) + xv.z, __high2float(p1) + xv.w };

    float s = v[0] + v[1] + v[2] + v[3];
    float s2 = v[0]*v[0] + v[1]*v[1] + v[2]*v[2] + v[3]*v[3];

#pragma unroll
    for (int o = 16; o > 0; o >>= 1) {
        s  += __shfl_xor_sync(0xFFFFFFFFu, s,  o);
        s2 += __shfl_xor_sync(0xFFFFFFFFu, s2, o);
    }
    __shared__ float rs[8], rs2[8];
    int wid = tid >> 5, lane = tid & 31;
    if (lane == 0) { rs[wid] = s; rs2[wid] = s2; }
    __syncthreads();
    if (wid == 0) {
        float a  = (lane < 8) ? rs[lane]  : 0.0f;
        float a2 = (lane < 8) ? rs2[lane] : 0.0f;
#pragma unroll
        for (int o = 4; o > 0; o >>= 1) {
            a  += __shfl_xor_sync(0xFFFFFFFFu, a,  o);
            a2 += __shfl_xor_sync(0xFFFFFFFFu, a2, o);
        }
        if (lane == 0) { rs[0] = a; rs2[0] = a2; }
    }
    __syncthreads();
    float mu  = rs[0]  * (1.0f / DIM);
    float var = rs2[0] * (1.0f / DIM) - mu * mu;
    float rstd = rsqrtf(var + LNEPS);

    const float* gp = gamma + tid * 4;
    const float* bp = beta  + tid * 4;
    float4 o4;
    o4.x = (v[0] - mu) * rstd * gp[0] + bp[0];
    o4.y = (v[1] - mu) * rstd * gp[1] + bp[1];
    o4.z = (v[2] - mu) * rstd * gp[2] + bp[2];
    o4.w = (v[3] - mu) * rstd * gp[3] + bp[3];
    *(float4*)(out + (size_t)row * DIM + tid * 4) = o4;
}

// ---------------- host launcher ----------------------------------------------
extern "C" void kernel_launch(void* const* d_in, const int* in_sizes, int n_in,
                              void* d_out, int out_size)
{
    (void)in_sizes; (void)n_in; (void)out_size;
    const float* x     = (const float*)d_in[0];
    const float* Wq    = (const float*)d_in[1];
    const float* Wk    = (const float*)d_in[2];
    const float* Wv    = (const float*)d_in[3];
    const float* Wo    = (const float*)d_in[4];
    const float* bo    = (const float*)d_in[5];
    const float* alpha = (const float*)d_in[6];
    const float* temp  = (const float*)d_in[7];
    const float* gamma = (const float*)d_in[8];
    const float* beta  = (const float*)d_in[9];
    float* out = (float*)d_out;

    __half *xh, *wh, *gm, *hk, *wpp, *w2p, *projh;
    cudaGetSymbolAddress((void**)&xh,    g_xh);
    cudaGetSymbolAddress((void**)&wh,    g_wh);
    cudaGetSymbolAddress((void**)&gm,    g_gm);
    cudaGetSymbolAddress((void**)&hk,    g_hk);
    cudaGetSymbolAddress((void**)&wpp,   g_wp);
    cudaGetSymbolAddress((void**)&w2p,   g_w2);
    cudaGetSymbolAddress((void**)&projh, g_projh);

    const int SMEM_GEMM = 65536;   // 2-stage * (16KB A + 16KB B)
    cudaFuncSetAttribute(gemm_f16,
                         cudaFuncAttributeMaxDynamicSharedMemorySize, SMEM_GEMM);
    cudaFuncSetAttribute(gsplit_kernel,
                         cudaFuncAttributeMaxDynamicSharedMemorySize, SMEM_GEMM);

    const size_t WSZ = (size_t)DIM * DIM;
    convw_kernel<<<dim3(DIM*DIM/2048, 4), 256>>>(Wq, Wk, Wv, Wo);

    // fused x conversion + transpose
    convx_kernel<<<dim3(DIM/64, SEQ/64, BATCH), 256>>>(x);

    // G_b = X_b^T X_b: split-K=2 f32 partials on triangle, then reduce+mirror
    gsplit_kernel<<<dim3(8, 8, BATCH*2), 256, SMEM_GEMM>>>();
    greduce_kernel<<<dim3(8, 8, BATCH), 256>>>();

    // Hk_b = Wk @ G_b
    gemm_f16<<<dim3(DIM/128, DIM/128, BATCH), 256, SMEM_GEMM>>>(
        wh + 1*WSZ, gm, nullptr, hk, DIM, DIM/64, DIM, DIM, 0, WSZ, WSZ);

    // per-head Gram blocks (i-split) + solve + softmax
    kkt2_kernel<<<dim3(BH, KS4), 256>>>();
    solve_kernel<<<BH, 256>>>(alpha, temp);

    // fold amap into weights
    fold1_kernel<<<dim3(BH, DIM/256), 256>>>();
    gemm_f16<<<dim3(DIM/128, DIM/128, BATCH), 256, SMEM_GEMM>>>(
        wh + 3*WSZ, wpp, nullptr, w2p, DIM, DIM/64, DIM, DIM, 0, WSZ, WSZ);

    // proj[b] = x[b] @ W2_b + bo  (fp16 out)
    gemm_f16<<<dim3(DIM/128, SEQ/128, BATCH), 256, SMEM_GEMM>>>(
        xh, w2p, bo, projh, DIM, DIM/64, DIM, DIM,
        (size_t)SEQ*DIM, WSZ, (size_t)SEQ*DIM);

    ln_kernel<<<MTOT, 256>>>(x, gamma, beta, out);
}

// round 13
// speedup vs baseline: 1.4367x; 1.4367x over previous
#include <cuda_runtime.h>
#include <cuda_fp16.h>
#include <cstdint>
#include <math.h>

#define BATCH 4
#define SEQ   4096
#define DIM   1024
#define NH    16
#define HD    64
#define BH    (BATCH*NH)          // 64
#define MTOT  (BATCH*SEQ)         // 16384
#define LNEPS 1e-5f
#define KS4   4                   // kkt2 i-splits

// ---------------- scratch (static device globals; no allocation) -------------
__device__ __align__(16) __half g_xh [(size_t)MTOT*DIM];
__device__ __align__(16) __half g_xt [(size_t)BATCH*DIM*SEQ];   // X^T per batch
__device__ __align__(16) __half g_wh [4][(size_t)DIM*DIM];
__device__ __align__(16) float  g_gp [(size_t)BATCH*2*DIM*DIM]; // G split-K partials
__device__ __align__(16) __half g_gm [(size_t)BATCH*DIM*DIM];   // G = X^T X
__device__ __align__(16) __half g_hk [(size_t)BATCH*DIM*DIM];   // Hk = Wk G
__device__ __align__(16) __half g_wp [(size_t)BATCH*DIM*DIM];   // folded W'
__device__ __align__(16) __half g_w2 [(size_t)BATCH*DIM*DIM];   // folded W2^T
__device__ __align__(16) __half g_projh[(size_t)MTOT*DIM];
__device__ float g_part[KS4*BH*2*HD*HD];
__device__ float g_amap[BH*HD*HD];

// ---------------- async copy / mma helpers ------------------------------------
#define CP16(dst_u32, src_ptr) \
    asm volatile("cp.async.cg.shared.global [%0], [%1], 16;\n" \
                 :: "r"(dst_u32), "l"(src_ptr))
#define CPCOMMIT() asm volatile("cp.async.commit_group;\n" ::: "memory")
#define CPWAIT1()  asm volatile("cp.async.wait_group 1;\n" ::: "memory")

__device__ __forceinline__ void ldsm4(unsigned r[4], unsigned addr) {
    asm volatile("ldmatrix.sync.aligned.m8n8.x4.shared.b16 {%0,%1,%2,%3}, [%4];"
                 : "=r"(r[0]), "=r"(r[1]), "=r"(r[2]), "=r"(r[3]) : "r"(addr));
}

__device__ __forceinline__ void mma16816(float* c, const unsigned a[4],
                                         unsigned b0, unsigned b1) {
    asm volatile(
        "mma.sync.aligned.m16n8k16.row.col.f32.f16.f16.f32 "
        "{%0,%1,%2,%3}, {%4,%5,%6,%7}, {%8,%9}, {%0,%1,%2,%3};"
        : "+f"(c[0]), "+f"(c[1]), "+f"(c[2]), "+f"(c[3])
        : "r"(a[0]), "r"(a[1]), "r"(a[2]), "r"(a[3]), "r"(b0), "r"(b1));
}

// ---------------- f32 -> fp16: all 4 weights in one launch ---------------------
__global__ __launch_bounds__(256) void convw_kernel(
    const float* __restrict__ w0, const float* __restrict__ w1,
    const float* __restrict__ w2, const float* __restrict__ w3)
{
    const float* srcs[4] = { w0, w1, w2, w3 };
    const float* src = srcs[blockIdx.y];
    __half* dst = &g_wh[blockIdx.y][0];
    size_t base = (size_t)(blockIdx.x * blockDim.x + threadIdx.x) * 8;
    float4 v0 = *(const float4*)(src + base);
    float4 v1 = *(const float4*)(src + base + 4);
    __half o[8];
    o[0] = __float2half_rn(v0.x); o[1] = __float2half_rn(v0.y);
    o[2] = __float2half_rn(v0.z); o[3] = __float2half_rn(v0.w);
    o[4] = __float2half_rn(v1.x); o[5] = __float2half_rn(v1.y);
    o[6] = __float2half_rn(v1.z); o[7] = __float2half_rn(v1.w);
    *(uint4*)(dst + base) = *(const uint4*)o;
}

// ---------- fused x(f32) -> xh(fp16 row-major) + xt(fp16 transposed) ----------
__global__ __launch_bounds__(256) void convx_kernel(const float* __restrict__ x)
{
    int ib = blockIdx.x, nb = blockIdx.y, b = blockIdx.z;
    __shared__ __half Ts[64][64];
    int tid = threadIdx.x;
    const float* src = x + ((size_t)(b * SEQ + nb * 64)) * DIM + ib * 64;
    __half* xh = g_xh + ((size_t)(b * SEQ + nb * 64)) * DIM + ib * 64;
#pragma unroll
    for (int it = 0; it < 2; ++it) {
        int idx = tid + it * 256;
        int r  = idx >> 3;
        int cc = idx & 7;
        float4 v0 = *(const float4*)(src + (size_t)r * DIM + cc * 8);
        float4 v1 = *(const float4*)(src + (size_t)r * DIM + cc * 8 + 4);
        __half o[8];
        o[0] = __float2half_rn(v0.x); o[1] = __float2half_rn(v0.y);
        o[2] = __float2half_rn(v0.z); o[3] = __float2half_rn(v0.w);
        o[4] = __float2half_rn(v1.x); o[5] = __float2half_rn(v1.y);
        o[6] = __float2half_rn(v1.z); o[7] = __float2half_rn(v1.w);
        *(uint4*)(xh + (size_t)r * DIM + cc * 8) = *(const uint4*)o;
        int ccs = cc ^ ((r >> 3) & 7);
        *(uint4*)&Ts[r][ccs * 8] = *(const uint4*)o;
    }
    __syncthreads();
    __half* dst = g_xt + ((size_t)b * DIM + ib * 64) * SEQ + nb * 64;
#pragma unroll
    for (int it = 0; it < 2; ++it) {
        int idx = tid + it * 256;
        int ng = idx & 7;
        int i  = idx >> 3;
        __half o[8];
#pragma unroll
        for (int k = 0; k < 8; ++k) {
            int n = ng * 8 + k;
            int cc = (i >> 3) ^ ((n >> 3) & 7);
            o[k] = Ts[n][cc * 8 + (i & 7)];
        }
        *(uint4*)(dst + (size_t)i * SEQ + ng * 8) = *(const uint4*)o;
    }
}

// ------------- G split-K GEMM: triangle tiles, f32 partial out ----------------
// 3-stage cp.async, 96KB smem.
__global__ __launch_bounds__(256) void gsplit_kernel()
{
    extern __shared__ __half sm[];
    const unsigned smem_base = (unsigned)__cvta_generic_to_shared(sm);
    const int tid  = threadIdx.x;
    const int lane = tid & 31;
    const int warp = tid >> 5;
    const int wm = (warp >> 2) * 64;
    const int wn = (warp & 3) * 32;
    const int bm = blockIdx.y * 128;
    const int bn = blockIdx.x * 128;
    if (bn > bm) return;
    const int b = blockIdx.z >> 1;
    const int sp = blockIdx.z & 1;
    const int g4 = lane >> 2;
    const int tg = lane & 3;

    const __half* A2 = g_xt + (size_t)b * DIM * SEQ;
    float* Cf = g_gp + (size_t)blockIdx.z * DIM * DIM;

    float acc[4][4][4];
#pragma unroll
    for (int t = 0; t < 4; ++t)
#pragma unroll
        for (int u = 0; u < 4; ++u)
#pragma unroll
            for (int r = 0; r < 4; ++r) acc[t][u][r] = 0.0f;

    auto load_chunk = [&](int kc, int bf) {
#pragma unroll
        for (int it = 0; it < 4; ++it) {
            int idx = tid + it * 256;
            int row = idx >> 3;
            int c8  = idx & 7;
            const __half* sa = A2 + (size_t)(bm + row) * SEQ + kc * 64 + c8 * 8;
            const __half* sb = A2 + (size_t)(bn + row) * SEQ + kc * 64 + c8 * 8;
            unsigned sw = (unsigned)((c8 ^ (row & 7)) * 16);
            CP16(smem_base + bf * 16384 + row * 128 + sw, sa);
            CP16(smem_base + 49152 + bf * 16384 + row * 128 + sw, sb);
        }
    };

    const int khalf = lane >> 4;
    int rowA[4], rowB[2];
#pragma unroll
    for (int t = 0; t < 4; ++t) rowA[t] = wm + t * 16 + (lane & 15);
#pragma unroll
    for (int p = 0; p < 2; ++p) rowB[p] = wn + p * 16 + (lane & 15);

    const int k0 = sp * 32;
    load_chunk(k0 + 0, 0); CPCOMMIT();
    load_chunk(k0 + 1, 1); CPCOMMIT();

    for (int kc = 0; kc < 32; ++kc) {
        CPWAIT1();
        __syncthreads();
        if (kc + 2 < 32) { load_chunk(k0 + kc + 2, (kc + 2) % 3); CPCOMMIT(); }

        const int bf = kc % 3;
        const unsigned abase = smem_base + bf * 16384;
        const unsigned bbase = smem_base + 49152 + bf * 16384;

#pragma unroll
        for (int s = 0; s < 4; ++s) {
            const int ch = s * 2 + khalf;
            unsigned a[4][4], bfr[2][4];
#pragma unroll
            for (int t = 0; t < 4; ++t)
                ldsm4(a[t], abase + rowA[t] * 128 +
                             (unsigned)((ch ^ (rowA[t] & 7)) * 16));
#pragma unroll
            for (int p = 0; p < 2; ++p)
                ldsm4(bfr[p], bbase + rowB[p] * 128 +
                              (unsigned)((ch ^ (rowB[p] & 7)) * 16));
#pragma unroll
            for (int t = 0; t < 4; ++t)
#pragma unroll
                for (int u = 0; u < 4; ++u) {
                    int p = u >> 1, h = u & 1;
                    mma16816(acc[t][u], a[t], bfr[p][h], bfr[p][2 + h]);
                }
        }
    }

#pragma unroll
    for (int t = 0; t < 4; ++t) {
        int r = bm + wm + t * 16 + g4;
#pragma unroll
        for (int u = 0; u < 4; ++u) {
            int c = bn + wn + u * 8 + tg * 2;
            *(float2*)&Cf[(size_t)r * DIM + c] =
                make_float2(acc[t][u][0], acc[t][u][1]);
            *(float2*)&Cf[(size_t)(r + 8) * DIM + c] =
                make_float2(acc[t][u][2], acc[t][u][3]);
        }
    }
}

// ------------- greduce: sum 2 partials -> fp16 G + symmetric mirror -----------
__global__ __launch_bounds__(256) void greduce_kernel()
{
    int bm = blockIdx.y * 128, bn = blockIdx.x * 128;
    if (bn > bm) return;
    int b = blockIdx.z;
    int tid = threadIdx.x;
    __shared__ __half S[128][132];

    const float* p0 = g_gp + (size_t)(b * 2 + 0) * DIM * DIM;
    const float* p1 = g_gp + (size_t)(b * 2 + 1) * DIM * DIM;
    __half* Gm = g_gm + (size_t)b * DIM * DIM;

#pragma unroll
    for (int it = 0; it < 16; ++it) {
        int idx = tid + it * 256;
        int r  = idx >> 5;
        int c4 = (idx & 31) * 4;
        size_t off = (size_t)(bm + r) * DIM + bn + c4;
        float4 a = *(const float4*)(p0 + off);
        float4 c = *(const float4*)(p1 + off);
        __half2 h0 = __floats2half2_rn(a.x + c.x, a.y + c.y);
        __half2 h1 = __floats2half2_rn(a.z + c.z, a.w + c.w);
        __half o[4];
        *(__half2*)&o[0] = h0;
        *(__half2*)&o[2] = h1;
        *(uint2*)&Gm[off] = *(const uint2*)o;
        *(__half2*)&S[r][c4]     = h0;
        *(__half2*)&S[r][c4 + 2] = h1;
    }

    if (bn < bm) {
        __syncthreads();
#pragma unroll
        for (int it = 0; it < 8; ++it) {
            int idx = tid + it * 256;
            int j  = idx >> 4;
            int i0 = (idx & 15) * 8;
            __half o[8];
#pragma unroll
            for (int k = 0; k < 8; ++k) o[k] = S[i0 + k][j];
            *(uint4*)&Gm[(size_t)(bn + j) * DIM + bm + i0] = *(const uint4*)o;
        }
    }
}

// ---------------- fp16 GEMM: C[m,n]=sum_k A[m,k]*B[n,k] (fp16 out) -----------
// 3-stage cp.async, 96KB smem.
__global__ __launch_bounds__(256) void gemm_f16(
    const __half* __restrict__ A0, const __half* __restrict__ B0,
    const float* __restrict__ bias, __half* __restrict__ Ch0, int N,
    int nck, int lda, int ldb, size_t strA, size_t strB, size_t strC)
{
    extern __shared__ __half sm[];
    const unsigned smem_base = (unsigned)__cvta_generic_to_shared(sm);
    const int tid  = threadIdx.x;
    const int lane = tid & 31;
    const int warp = tid >> 5;
    const int wm = (warp >> 2) * 64;
    const int wn = (warp & 3) * 32;
    const int bm = blockIdx.y * 128;
    const int bn = blockIdx.x * 128;
    const int z  = blockIdx.z;
    const int g4 = lane >> 2;
    const int tg = lane & 3;

    const __half* A2 = A0 + (size_t)z * strA;
    const __half* B2 = B0 + (size_t)z * strB;
    __half* Ch = Ch0 + (size_t)z * strC;

    float acc[4][4][4];
#pragma unroll
    for (int t = 0; t < 4; ++t)
#pragma unroll
        for (int u = 0; u < 4; ++u)
#pragma unroll
            for (int r = 0; r < 4; ++r) acc[t][u][r] = 0.0f;

    auto load_chunk = [&](int kc, int bf) {
#pragma unroll
        for (int it = 0; it < 4; ++it) {
            int idx = tid + it * 256;
            int row = idx >> 3;
            int c8  = idx & 7;
            const __half* sa = A2 + (size_t)(bm + row) * lda + kc * 64 + c8 * 8;
            const __half* sb = B2 + (size_t)(bn + row) * ldb + kc * 64 + c8 * 8;
            unsigned sw = (unsigned)((c8 ^ (row & 7)) * 16);
            CP16(smem_base + bf * 16384 + row * 128 + sw, sa);
            CP16(smem_base + 49152 + bf * 16384 + row * 128 + sw, sb);
        }
    };

    const int khalf = lane >> 4;
    int rowA[4], rowB[2];
#pragma unroll
    for (int t = 0; t < 4; ++t) rowA[t] = wm + t * 16 + (lane & 15);
#pragma unroll
    for (int p = 0; p < 2; ++p) rowB[p] = wn + p * 16 + (lane & 15);

    load_chunk(0, 0); CPCOMMIT();
    load_chunk(1, 1); CPCOMMIT();

    for (int kc = 0; kc < nck; ++kc) {
        CPWAIT1();
        __syncthreads();
        if (kc + 2 < nck) { load_chunk(kc + 2, (kc + 2) % 3); CPCOMMIT(); }

        const int bf = kc % 3;
        const unsigned abase = smem_base + bf * 16384;
        const unsigned bbase = smem_base + 49152 + bf * 16384;

#pragma unroll
        for (int s = 0; s < 4; ++s) {
            const int ch = s * 2 + khalf;
            unsigned a[4][4], b[2][4];
#pragma unroll
            for (int t = 0; t < 4; ++t)
                ldsm4(a[t], abase + rowA[t] * 128 +
                             (unsigned)((ch ^ (rowA[t] & 7)) * 16));
#pragma unroll
            for (int p = 0; p < 2; ++p)
                ldsm4(b[p], bbase + rowB[p] * 128 +
                             (unsigned)((ch ^ (rowB[p] & 7)) * 16));
#pragma unroll
            for (int t = 0; t < 4; ++t)
#pragma unroll
                for (int u = 0; u < 4; ++u) {
                    int p = u >> 1, h = u & 1;
                    mma16816(acc[t][u], a[t], b[p][h], b[p][2 + h]);
                }
        }
    }

#pragma unroll
    for (int t = 0; t < 4; ++t) {
        int r = bm + wm + t * 16 + g4;
#pragma unroll
        for (int u = 0; u < 4; ++u) {
            int c = bn + wn + u * 8 + tg * 2;
            float b0 = 0.0f, b1 = 0.0f;
            if (bias) { b0 = bias[c]; b1 = bias[c + 1]; }
            *(__half2*)&Ch[(size_t)r * N + c] =
                __floats2half2_rn(acc[t][u][0] + b0, acc[t][u][1] + b1);
            *(__half2*)&Ch[(size_t)(r + 8) * N + c] =
                __floats2half2_rn(acc[t][u][2] + b0, acc[t][u][3] + b1);
        }
    }
}

// -------- kkt2: kk/kv partials from Hk_h · [Wk_h | Wv_h]^T, i-split -----------
__global__ __launch_bounds__(256) void kkt2_kernel()
{
    int bh = blockIdx.x;
    int sp = blockIdx.y;
    int b = bh >> 4, h = bh & 15;
    const __half* hk = g_hk    + (size_t)b * DIM * DIM + (size_t)(h * HD) * DIM;
    const __half* wk = g_wh[1] + (size_t)(h * HD) * DIM;
    const __half* wv = g_wh[2] + (size_t)(h * HD) * DIM;

    __shared__ __half Hs[64][72];
    __shared__ __half Ts[128][72];
    const unsigned hb = (unsigned)__cvta_generic_to_shared(&Hs[0][0]);
    const unsigned tb = (unsigned)__cvta_generic_to_shared(&Ts[0][0]);
    const int tid = threadIdx.x;
    const int lane = tid & 31;
    const int warp = tid >> 5;
    const int wm = (warp >> 2) * 32;
    const int wn = (warp & 3) * 32;
    const int g4 = lane >> 2;
    const int tg = lane & 3;

    float acc[2][4][4];
#pragma unroll
    for (int mt = 0; mt < 2; ++mt)
#pragma unroll
        for (int u = 0; u < 4; ++u)
#pragma unroll
            for (int r = 0; r < 4; ++r) acc[mt][u][r] = 0.0f;

    const int khalf = lane >> 4;
    int rowA[2], rowB[2];
#pragma unroll
    for (int mt = 0; mt < 2; ++mt) rowA[mt] = wm + mt * 16 + (lane & 15);
#pragma unroll
    for (int p = 0; p < 2; ++p) rowB[p] = wn + p * 16 + (lane & 15);

    for (int i0 = sp * 256; i0 < sp * 256 + 256; i0 += 64) {
        __syncthreads();
#pragma unroll
        for (int it = 0; it < 2; ++it) {
            int idx = tid + it * 256;
            int r = idx >> 3, c8 = (idx & 7) * 8;
            *(uint4*)&Hs[r][c8] = *(const uint4*)(hk + (size_t)r * DIM + i0 + c8);
        }
#pragma unroll
        for (int it = 0; it < 4; ++it) {
            int idx = tid + it * 256;
            int r = idx >> 3, c8 = (idx & 7) * 8;
            const __half* src = (r < 64 ? wk + (size_t)r * DIM
                                        : wv + (size_t)(r - 64) * DIM) + i0 + c8;
            *(uint4*)&Ts[r][c8] = *(const uint4*)src;
        }
        __syncthreads();

#pragma unroll
        for (int ks = 0; ks < 4; ++ks) {
            unsigned a[2][4], bfr[2][4];
            unsigned colb = (unsigned)(ks * 32 + khalf * 16);
#pragma unroll
            for (int mt = 0; mt < 2; ++mt)
                ldsm4(a[mt], hb + rowA[mt] * 144 + colb);
#pragma unroll
            for (int p = 0; p < 2; ++p)
                ldsm4(bfr[p], tb + rowB[p] * 144 + colb);
#pragma unroll
            for (int mt = 0; mt < 2; ++mt)
#pragma unroll
                for (int u = 0; u < 4; ++u) {
                    int p = u >> 1, hh = u & 1;
                    mma16816(acc[mt][u], a[mt], bfr[p][hh], bfr[p][2 + hh]);
                }
        }
    }

    float* pkk = g_part + (size_t)(sp * BH + bh) * 2 * 4096;
    float* pkv = pkk + 4096;
#pragma unroll
    for (int mt = 0; mt < 2; ++mt) {
        int d = wm + mt * 16 + g4;
#pragma unroll
        for (int u = 0; u < 4; ++u) {
            int j = wn + u * 8 + tg * 2;
            float* dst = (j < 64) ? (pkk + d * 64 + j) : (pkv + d * 64 + (j - 64));
            *(float2*)dst = make_float2(acc[mt][u][0], acc[mt][u][1]);
            float* dst2 = (j < 64) ? (pkk + (d + 8) * 64 + j)
                                   : (pkv + (d + 8) * 64 + (j - 64));
            *(float2*)dst2 = make_float2(acc[mt][u][2], acc[mt][u][3]);
        }
    }
}

// ------- reduce partials, solve (kk+aI) X = ktv, column softmax ---------------
__global__ __launch_bounds__(256) void solve_kernel(
    const float* __restrict__ alpha_p, const float* __restrict__ temp_p)
{
    int bh = blockIdx.x;
    __shared__ float A[64][65];
    __shared__ float X[64][65];
    int tid = threadIdx.x;

    for (int i = tid; i < 4096; i += 256) {
        float skk = 0.0f, skv = 0.0f;
#pragma unroll
        for (int s = 0; s < KS4; ++s) {
            const float* p = g_part + ((size_t)(s * BH + bh) * 2) * 4096;
            skk += p[i];
            skv += p[4096 + i];
        }
        A[i >> 6][i & 63] = skk;
        X[i >> 6][i & 63] = skv;
    }
    __syncthreads();
    if (tid < 64) A[tid][tid] += alpha_p[0];

    int r  = tid >> 2;
    int c0 = (tid & 3) * 16;
    for (int pp = 0; pp < 64; ++pp) {
        __syncthreads();
        float pinv = 1.0f / A[pp][pp];
        __syncthreads();
        if (tid < 64)      A[pp][tid]      *= pinv;
        else if (tid < 128) X[pp][tid - 64] *= pinv;
        __syncthreads();
        float f = (r != pp) ? A[r][pp] : 0.0f;
        __syncthreads();
        if (r != pp) {
#pragma unroll
            for (int c = 0; c < 16; ++c) {
                A[r][c0 + c] = fmaf(-f, A[pp][c0 + c], A[r][c0 + c]);
                X[r][c0 + c] = fmaf(-f, X[pp][c0 + c], X[r][c0 + c]);
            }
        }
    }
    __syncthreads();

    if (tid < 64) {
        float invt = 1.0f / temp_p[0];
        float mx = -1e30f;
        for (int d = 0; d < 64; ++d) mx = fmaxf(mx, X[d][tid] * invt);
        float s = 0.0f;
        for (int d = 0; d < 64; ++d) s += expf(X[d][tid] * invt - mx);
        float inv_s = 1.0f / s;
        for (int d = 0; d < 64; ++d)
            g_amap[(size_t)bh * 4096 + d * 64 + tid] =
                expf(X[d][tid] * invt - mx) * inv_s;
    }
}

// ---------- fold1: W'_b[din, h*64+j] = sum_e Wq[h*64+e, din] * amap[e, j] -----
__global__ __launch_bounds__(256) void fold1_kernel()
{
    int bh = blockIdx.x;
    int chunk = blockIdx.y;
    int b = bh >> 4, h = bh & 15;

    __shared__ __half WqS[64][256];
    __shared__ float  AmS[64][64];
    int tid = threadIdx.x;

    const __half* wq = g_wh[0] + (size_t)(h * 64) * DIM + chunk * 256;
#pragma unroll
    for (int it = 0; it < 8; ++it) {
        int idx = tid + it * 256;
        int e = idx >> 5;
        int c8 = (idx & 31) * 8;
        *(uint4*)&WqS[e][c8] = *(const uint4*)(wq + (size_t)e * DIM + c8);
    }
#pragma unroll
    for (int it = 0; it < 4; ++it) {
        int idx = tid + it * 256;
        int e = idx >> 4;
        int j4 = (idx & 15) * 4;
        *(float4*)&AmS[e][j4] =
            *(const float4*)&g_amap[(size_t)bh * 4096 + e * 64 + j4];
    }
    __syncthreads();

    int ty = tid >> 3;
    int tx = tid & 7;
    float acc[8][8];
#pragma unroll
    for (int i = 0; i < 8; ++i)
#pragma unroll
        for (int j = 0; j < 8; ++j) acc[i][j] = 0.0f;

#pragma unroll 4
    for (int e = 0; e < 64; ++e) {
        __half ah[8];
        *(uint4*)ah = *(const uint4*)&WqS[e][ty * 8];
        float bv[8];
        float4 b0 = *(const float4*)&AmS[e][tx * 8];
        float4 b1 = *(const float4*)&AmS[e][tx * 8 + 4];
        bv[0]=b0.x; bv[1]=b0.y; bv[2]=b0.z; bv[3]=b0.w;
        bv[4]=b1.x; bv[5]=b1.y; bv[6]=b1.z; bv[7]=b1.w;
#pragma unroll
        for (int i = 0; i < 8; ++i) {
            float av = __half2float(ah[i]);
#pragma unroll
            for (int j = 0; j < 8; ++j) acc[i][j] = fmaf(av, bv[j], acc[i][j]);
        }
    }

    __half* wp = g_wp + (size_t)b * DIM * DIM;
#pragma unroll
    for (int i = 0; i < 8; ++i) {
        int din = chunk * 256 + ty * 8 + i;
        __half o[8];
#pragma unroll
        for (int j = 0; j < 8; ++j) o[j] = __float2half_rn(acc[i][j]);
        *(uint4*)&wp[(size_t)din * DIM + h * 64 + tx * 8] = *(const uint4*)o;
    }
}

// ---------------- LayerNorm(proj(fp16) + x(f32)), warp-per-row ----------------
// block 256 = 8 warps = 8 rows; grid MTOT/8 = 2048
__global__ __launch_bounds__(256) void ln_kernel(
    const float* __restrict__ x, const float* __restrict__ gamma,
    const float* __restrict__ beta, float* __restrict__ out)
{
    int wid = threadIdx.x >> 5;
    int lane = threadIdx.x & 31;
    int row = blockIdx.x * 8 + wid;
    const __half* pr = g_projh + (size_t)row * DIM;
    const float*  xr = x       + (size_t)row * DIM;

    float v[32];
    float s = 0.0f, s2 = 0.0f;
#pragma unroll
    for (int c = 0; c < 8; ++c) {
        int base = c * 128 + lane * 4;
        uint2 pu = *(const uint2*)(pr + base);
        __half2 p0 = *reinterpret_cast<__half2*>(&pu.x);
        __half2 p1 = *reinterpret_cast<__half2*>(&pu.y);
        float4 xv = *(const float4*)(xr + base);
        float* vc = v + c * 4;
        vc[0] = __low2float(p0) + xv.x;
        vc[1] = __high2float(p0) + xv.y;
        vc[2] = __low2float(p1) + xv.z;
        vc[3] = __high2float(p1) + xv.w;
#pragma unroll
        for (int k = 0; k < 4; ++k) { s += vc[k]; s2 += vc[k] * vc[k]; }
    }

#pragma unroll
    for (int o = 16; o > 0; o >>= 1) {
        s  += __shfl_xor_sync(0xFFFFFFFFu, s,  o);
        s2 += __shfl_xor_sync(0xFFFFFFFFu, s2, o);
    }
    float mu  = s  * (1.0f / DIM);
    float var = s2 * (1.0f / DIM) - mu * mu;
    float rstd = rsqrtf(var + LNEPS);

#pragma unroll
    for (int c = 0; c < 8; ++c) {
        int base = c * 128 + lane * 4;
        float4 gp = *(const float4*)(gamma + base);
        float4 bp = *(const float4*)(beta  + base);
        float* vc = v + c * 4;
        float4 o4;
        o4.x = (vc[0] - mu) * rstd * gp.x + bp.x;
        o4.y = (vc[1] - mu) * rstd * gp.y + bp.y;
        o4.z = (vc[2] - mu) * rstd * gp.z + bp.z;
        o4.w = (vc[3] - mu) * rstd * gp.w + bp.w;
        *(float4*)(out + (size_t)row * DIM + base) = o4;
    }
}

// ---------------- host launcher ----------------------------------------------
extern "C" void kernel_launch(void* const* d_in, const int* in_sizes, int n_in,
                              void* d_out, int out_size)
{
    (void)in_sizes; (void)n_in; (void)out_size;
    const float* x     = (const float*)d_in[0];
    const float* Wq    = (const float*)d_in[1];
    const float* Wk    = (const float*)d_in[2];
    const float* Wv    = (const float*)d_in[3];
    const float* Wo    = (const float*)d_in[4];
    const float* bo    = (const float*)d_in[5];
    const float* alpha = (const float*)d_in[6];
    const float* temp  = (const float*)d_in[7];
    const float* gamma = (const float*)d_in[8];
    const float* beta  = (const float*)d_in[9];
    float* out = (float*)d_out;

    __half *xh, *wh, *gm, *hk, *wpp, *w2p, *projh;
    cudaGetSymbolAddress((void**)&xh,    g_xh);
    cudaGetSymbolAddress((void**)&wh,    g_wh);
    cudaGetSymbolAddress((void**)&gm,    g_gm);
    cudaGetSymbolAddress((void**)&hk,    g_hk);
    cudaGetSymbolAddress((void**)&wpp,   g_wp);
    cudaGetSymbolAddress((void**)&w2p,   g_w2);
    cudaGetSymbolAddress((void**)&projh, g_projh);

    const int SMEM_GEMM = 98304;   // 3-stage * (16KB A + 16KB B)
    cudaFuncSetAttribute(gemm_f16,
                         cudaFuncAttributeMaxDynamicSharedMemorySize, SMEM_GEMM);
    cudaFuncSetAttribute(gsplit_kernel,
                         cudaFuncAttributeMaxDynamicSharedMemorySize, SMEM_GEMM);

    const size_t WSZ = (size_t)DIM * DIM;
    convw_kernel<<<dim3(DIM*DIM/2048, 4), 256>>>(Wq, Wk, Wv, Wo);

    // fused x conversion + transpose
    convx_kernel<<<dim3(DIM/64, SEQ/64, BATCH), 256>>>(x);

    // G_b = X_b^T X_b: split-K=2 f32 partials on triangle, then reduce+mirror
    gsplit_kernel<<<dim3(8, 8, BATCH*2), 256, SMEM_GEMM>>>();
    greduce_kernel<<<dim3(8, 8, BATCH), 256>>>();

    // Hk_b = Wk @ G_b
    gemm_f16<<<dim3(DIM/128, DIM/128, BATCH), 256, SMEM_GEMM>>>(
        wh + 1*WSZ, gm, nullptr, hk, DIM, DIM/64, DIM, DIM, 0, WSZ, WSZ);

    // per-head Gram blocks (i-split) + solve + softmax
    kkt2_kernel<<<dim3(BH, KS4), 256>>>();
    solve_kernel<<<BH, 256>>>(alpha, temp);

    // fold amap into weights
    fold1_kernel<<<dim3(BH, DIM/256), 256>>>();
    gemm_f16<<<dim3(DIM/128, DIM/128, BATCH), 256, SMEM_GEMM>>>(
        wh + 3*WSZ, wpp, nullptr, w2p, DIM, DIM/64, DIM, DIM, 0, WSZ, WSZ);

    // proj[b] = x[b] @ W2_b + bo  (fp16 out)
    gemm_f16<<<dim3(DIM/128, SEQ/128, BATCH), 256, SMEM_GEMM>>>(
        xh, w2p, bo, projh, DIM, DIM/64, DIM, DIM,
        (size_t)SEQ*DIM, WSZ, (size_t)SEQ*DIM);

    ln_kernel<<<MTOT/8, 256>>>(x, gamma, beta, out);
}

// round 14
// speedup vs baseline: 1.4609x; 1.0169x over previous
#include <cuda_runtime.h>
#include <cuda_fp16.h>
#include <cstdint>
#include <math.h>

#define BATCH 4
#define SEQ   4096
#define DIM   1024
#define NH    16
#define HD    64
#define BH    (BATCH*NH)          // 64
#define MTOT  (BATCH*SEQ)         // 16384
#define LNEPS 1e-5f

// ---------------- scratch (static device globals; no allocation) -------------
__device__ __align__(16) __half g_xh [(size_t)MTOT*DIM];
__device__ __align__(16) __half g_xt [(size_t)BATCH*DIM*SEQ];   // X^T per batch
__device__ __align__(16) __half g_wh [4][(size_t)DIM*DIM];
__device__ __align__(16) float  g_gp [(size_t)BATCH*2*DIM*DIM]; // G split-K partials
__device__ __align__(16) __half g_gm [(size_t)BATCH*DIM*DIM];   // G = X^T X
__device__ __align__(16) __half g_hk [(size_t)BATCH*DIM*DIM];   // Hk = Wk G
__device__ __align__(16) __half g_wp [(size_t)BATCH*DIM*DIM];   // folded W'
__device__ __align__(16) __half g_w2 [(size_t)BATCH*DIM*DIM];   // folded W2^T
__device__ __align__(16) __half g_projh[(size_t)MTOT*DIM];
__device__ float g_amap[BH*HD*HD];

// ---------------- async copy / mma helpers ------------------------------------
#define CP16(dst_u32, src_ptr) \
    asm volatile("cp.async.cg.shared.global [%0], [%1], 16;\n" \
                 :: "r"(dst_u32), "l"(src_ptr))
#define CPCOMMIT() asm volatile("cp.async.commit_group;\n" ::: "memory")
#define CPWAIT1()  asm volatile("cp.async.wait_group 1;\n" ::: "memory")

__device__ __forceinline__ void ldsm4(unsigned r[4], unsigned addr) {
    asm volatile("ldmatrix.sync.aligned.m8n8.x4.shared.b16 {%0,%1,%2,%3}, [%4];"
                 : "=r"(r[0]), "=r"(r[1]), "=r"(r[2]), "=r"(r[3]) : "r"(addr));
}

__device__ __forceinline__ void mma16816(float* c, const unsigned a[4],
                                         unsigned b0, unsigned b1) {
    asm volatile(
        "mma.sync.aligned.m16n8k16.row.col.f32.f16.f16.f32 "
        "{%0,%1,%2,%3}, {%4,%5,%6,%7}, {%8,%9}, {%0,%1,%2,%3};"
        : "+f"(c[0]), "+f"(c[1]), "+f"(c[2]), "+f"(c[3])
        : "r"(a[0]), "r"(a[1]), "r"(a[2]), "r"(a[3]), "r"(b0), "r"(b1));
}

__device__ __forceinline__ void tri_idx(int t, int& I, int& J) {
    int acc = 0; I = 0;
    while (acc + I + 1 <= t) { acc += I + 1; ++I; }
    J = t - acc;
}

// ---- conv_all: z<BATCH -> x(f32)->xh+xt; z==BATCH -> 4 weights -> fp16 -------
__global__ __launch_bounds__(256) void conv_all(
    const float* __restrict__ x,
    const float* __restrict__ w0, const float* __restrict__ w1,
    const float* __restrict__ w2, const float* __restrict__ w3)
{
    int tid = threadIdx.x;
    if (blockIdx.z == BATCH) {
        const float* srcs[4] = { w0, w1, w2, w3 };
        int lb = blockIdx.y * 16 + blockIdx.x;      // 0..1023
#pragma unroll
        for (int it = 0; it < 2; ++it) {
            size_t idx = (size_t)lb * 4096 + it * 2048 + tid * 8;
            int wsel = (int)(idx >> 20);
            size_t off = idx & ((1u << 20) - 1);
            const float* src = srcs[wsel];
            float4 v0 = *(const float4*)(src + off);
            float4 v1 = *(const float4*)(src + off + 4);
            __half o[8];
            o[0] = __float2half_rn(v0.x); o[1] = __float2half_rn(v0.y);
            o[2] = __float2half_rn(v0.z); o[3] = __float2half_rn(v0.w);
            o[4] = __float2half_rn(v1.x); o[5] = __float2half_rn(v1.y);
            o[6] = __float2half_rn(v1.z); o[7] = __float2half_rn(v1.w);
            *(uint4*)(&g_wh[wsel][0] + off) = *(const uint4*)o;
        }
        return;
    }
    int ib = blockIdx.x, nb = blockIdx.y, b = blockIdx.z;
    __shared__ __half Ts[64][64];
    const float* src = x + ((size_t)(b * SEQ + nb * 64)) * DIM + ib * 64;
    __half* xh = g_xh + ((size_t)(b * SEQ + nb * 64)) * DIM + ib * 64;
#pragma unroll
    for (int it = 0; it < 2; ++it) {
        int idx = tid + it * 256;
        int r  = idx >> 3;
        int cc = idx & 7;
        float4 v0 = *(const float4*)(src + (size_t)r * DIM + cc * 8);
        float4 v1 = *(const float4*)(src + (size_t)r * DIM + cc * 8 + 4);
        __half o[8];
        o[0] = __float2half_rn(v0.x); o[1] = __float2half_rn(v0.y);
        o[2] = __float2half_rn(v0.z); o[3] = __float2half_rn(v0.w);
        o[4] = __float2half_rn(v1.x); o[5] = __float2half_rn(v1.y);
        o[6] = __float2half_rn(v1.z); o[7] = __float2half_rn(v1.w);
        *(uint4*)(xh + (size_t)r * DIM + cc * 8) = *(const uint4*)o;
        int ccs = cc ^ ((r >> 3) & 7);
        *(uint4*)&Ts[r][ccs * 8] = *(const uint4*)o;
    }
    __syncthreads();
    __half* dst = g_xt + ((size_t)b * DIM + ib * 64) * SEQ + nb * 64;
#pragma unroll
    for (int it = 0; it < 2; ++it) {
        int idx = tid + it * 256;
        int ng = idx & 7;
        int i  = idx >> 3;
        __half o[8];
#pragma unroll
        for (int k = 0; k < 8; ++k) {
            int n = ng * 8 + k;
            int cc = (i >> 3) ^ ((n >> 3) & 7);
            o[k] = Ts[n][cc * 8 + (i & 7)];
        }
        *(uint4*)(dst + (size_t)i * SEQ + ng * 8) = *(const uint4*)o;
    }
}

// ------------- G split-K GEMM: triangle-indexed tiles, f32 partial out --------
// grid (36, 1, BATCH*2). 3-stage cp.async, 96KB smem.
__global__ __launch_bounds__(256) void gsplit_kernel()
{
    extern __shared__ __half sm[];
    const unsigned smem_base = (unsigned)__cvta_generic_to_shared(sm);
    const int tid  = threadIdx.x;
    const int lane = tid & 31;
    const int warp = tid >> 5;
    const int wm = (warp >> 2) * 64;
    const int wn = (warp & 3) * 32;
    int I, J;
    tri_idx(blockIdx.x, I, J);
    const int bm = I * 128;
    const int bn = J * 128;
    const int b = blockIdx.z >> 1;
    const int sp = blockIdx.z & 1;
    const int g4 = lane >> 2;
    const int tg = lane & 3;

    const __half* A2 = g_xt + (size_t)b * DIM * SEQ;
    float* Cf = g_gp + (size_t)blockIdx.z * DIM * DIM;

    float acc[4][4][4];
#pragma unroll
    for (int t = 0; t < 4; ++t)
#pragma unroll
        for (int u = 0; u < 4; ++u)
#pragma unroll
            for (int r = 0; r < 4; ++r) acc[t][u][r] = 0.0f;

    auto load_chunk = [&](int kc, int bf) {
#pragma unroll
        for (int it = 0; it < 4; ++it) {
            int idx = tid + it * 256;
            int row = idx >> 3;
            int c8  = idx & 7;
            const __half* sa = A2 + (size_t)(bm + row) * SEQ + kc * 64 + c8 * 8;
            const __half* sb = A2 + (size_t)(bn + row) * SEQ + kc * 64 + c8 * 8;
            unsigned sw = (unsigned)((c8 ^ (row & 7)) * 16);
            CP16(smem_base + bf * 16384 + row * 128 + sw, sa);
            CP16(smem_base + 49152 + bf * 16384 + row * 128 + sw, sb);
        }
    };

    const int khalf = lane >> 4;
    int rowA[4], rowB[2];
#pragma unroll
    for (int t = 0; t < 4; ++t) rowA[t] = wm + t * 16 + (lane & 15);
#pragma unroll
    for (int p = 0; p < 2; ++p) rowB[p] = wn + p * 16 + (lane & 15);

    const int k0 = sp * 32;
    load_chunk(k0 + 0, 0); CPCOMMIT();
    load_chunk(k0 + 1, 1); CPCOMMIT();

    for (int kc = 0; kc < 32; ++kc) {
        CPWAIT1();
        __syncthreads();
        if (kc + 2 < 32) { load_chunk(k0 + kc + 2, (kc + 2) % 3); CPCOMMIT(); }

        const int bf = kc % 3;
        const unsigned abase = smem_base + bf * 16384;
        const unsigned bbase = smem_base + 49152 + bf * 16384;

#pragma unroll
        for (int s = 0; s < 4; ++s) {
            const int ch = s * 2 + khalf;
            unsigned a[4][4], bfr[2][4];
#pragma unroll
            for (int t = 0; t < 4; ++t)
                ldsm4(a[t], abase + rowA[t] * 128 +
                             (unsigned)((ch ^ (rowA[t] & 7)) * 16));
#pragma unroll
            for (int p = 0; p < 2; ++p)
                ldsm4(bfr[p], bbase + rowB[p] * 128 +
                              (unsigned)((ch ^ (rowB[p] & 7)) * 16));
#pragma unroll
            for (int t = 0; t < 4; ++t)
#pragma unroll
                for (int u = 0; u < 4; ++u) {
                    int p = u >> 1, h = u & 1;
                    mma16816(acc[t][u], a[t], bfr[p][h], bfr[p][2 + h]);
                }
        }
    }

#pragma unroll
    for (int t = 0; t < 4; ++t) {
        int r = bm + wm + t * 16 + g4;
#pragma unroll
        for (int u = 0; u < 4; ++u) {
            int c = bn + wn + u * 8 + tg * 2;
            *(float2*)&Cf[(size_t)r * DIM + c] =
                make_float2(acc[t][u][0], acc[t][u][1]);
            *(float2*)&Cf[(size_t)(r + 8) * DIM + c] =
                make_float2(acc[t][u][2], acc[t][u][3]);
        }
    }
}

// ------------- greduce: sum 2 partials -> fp16 G + mirror; half-tiles ---------
// grid (72, 1, BATCH): blockIdx.x = tile*2 + half. Each CTA: 64 rows of tile.
__global__ __launch_bounds__(256) void greduce_kernel()
{
    int I, J;
    tri_idx(blockIdx.x >> 1, I, J);
    int half = blockIdx.x & 1;
    int bm = I * 128, bn = J * 128;
    int b = blockIdx.z;
    int tid = threadIdx.x;
    __shared__ __half S[64][132];

    const float* p0 = g_gp + (size_t)(b * 2 + 0) * DIM * DIM;
    const float* p1 = g_gp + (size_t)(b * 2 + 1) * DIM * DIM;
    __half* Gm = g_gm + (size_t)b * DIM * DIM;
    int rbase = bm + half * 64;

#pragma unroll
    for (int it = 0; it < 8; ++it) {
        int idx = tid + it * 256;              // 2048 float4 groups
        int r  = idx >> 5;                     // 0..63
        int c4 = (idx & 31) * 4;
        size_t off = (size_t)(rbase + r) * DIM + bn + c4;
        float4 a = *(const float4*)(p0 + off);
        float4 c = *(const float4*)(p1 + off);
        __half2 h0 = __floats2half2_rn(a.x + c.x, a.y + c.y);
        __half2 h1 = __floats2half2_rn(a.z + c.z, a.w + c.w);
        __half o[4];
        *(__half2*)&o[0] = h0;
        *(__half2*)&o[2] = h1;
        *(uint2*)&Gm[off] = *(const uint2*)o;
        *(__half2*)&S[r][c4]     = h0;
        *(__half2*)&S[r][c4 + 2] = h1;
    }

    if (bn < bm) {
        __syncthreads();
#pragma unroll
        for (int it = 0; it < 4; ++it) {
            int idx = tid + it * 256;          // 1024 uint4 = 128 j x 8 i-chunks
            int j  = idx >> 3;
            int i0 = (idx & 7) * 8;
            __half o[8];
#pragma unroll
            for (int k = 0; k < 8; ++k) o[k] = S[i0 + k][j];
            *(uint4*)&Gm[(size_t)(bn + j) * DIM + rbase + i0] = *(const uint4*)o;
        }
    }
}

// ---------------- fp16 GEMM: C[m,n]=sum_k A[m,k]*B[n,k] (fp16 out) -----------
__global__ __launch_bounds__(256) void gemm_f16(
    const __half* __restrict__ A0, const __half* __restrict__ B0,
    const float* __restrict__ bias, __half* __restrict__ Ch0, int N,
    int nck, int lda, int ldb, size_t strA, size_t strB, size_t strC)
{
    extern __shared__ __half sm[];
    const unsigned smem_base = (unsigned)__cvta_generic_to_shared(sm);
    const int tid  = threadIdx.x;
    const int lane = tid & 31;
    const int warp = tid >> 5;
    const int wm = (warp >> 2) * 64;
    const int wn = (warp & 3) * 32;
    const int bm = blockIdx.y * 128;
    const int bn = blockIdx.x * 128;
    const int z  = blockIdx.z;
    const int g4 = lane >> 2;
    const int tg = lane & 3;

    const __half* A2 = A0 + (size_t)z * strA;
    const __half* B2 = B0 + (size_t)z * strB;
    __half* Ch = Ch0 + (size_t)z * strC;

    float acc[4][4][4];
#pragma unroll
    for (int t = 0; t < 4; ++t)
#pragma unroll
        for (int u = 0; u < 4; ++u)
#pragma unroll
            for (int r = 0; r < 4; ++r) acc[t][u][r] = 0.0f;

    auto load_chunk = [&](int kc, int bf) {
#pragma unroll
        for (int it = 0; it < 4; ++it) {
            int idx = tid + it * 256;
            int row = idx >> 3;
            int c8  = idx & 7;
            const __half* sa = A2 + (size_t)(bm + row) * lda + kc * 64 + c8 * 8;
            const __half* sb = B2 + (size_t)(bn + row) * ldb + kc * 64 + c8 * 8;
            unsigned sw = (unsigned)((c8 ^ (row & 7)) * 16);
            CP16(smem_base + bf * 16384 + row * 128 + sw, sa);
            CP16(smem_base + 49152 + bf * 16384 + row * 128 + sw, sb);
        }
    };

    const int khalf = lane >> 4;
    int rowA[4], rowB[2];
#pragma unroll
    for (int t = 0; t < 4; ++t) rowA[t] = wm + t * 16 + (lane & 15);
#pragma unroll
    for (int p = 0; p < 2; ++p) rowB[p] = wn + p * 16 + (lane & 15);

    load_chunk(0, 0); CPCOMMIT();
    load_chunk(1, 1); CPCOMMIT();

    for (int kc = 0; kc < nck; ++kc) {
        CPWAIT1();
        __syncthreads();
        if (kc + 2 < nck) { load_chunk(kc + 2, (kc + 2) % 3); CPCOMMIT(); }

        const int bf = kc % 3;
        const unsigned abase = smem_base + bf * 16384;
        const unsigned bbase = smem_base + 49152 + bf * 16384;

#pragma unroll
        for (int s = 0; s < 4; ++s) {
            const int ch = s * 2 + khalf;
            unsigned a[4][4], b[2][4];
#pragma unroll
            for (int t = 0; t < 4; ++t)
                ldsm4(a[t], abase + rowA[t] * 128 +
                             (unsigned)((ch ^ (rowA[t] & 7)) * 16));
#pragma unroll
            for (int p = 0; p < 2; ++p)
                ldsm4(b[p], bbase + rowB[p] * 128 +
                             (unsigned)((ch ^ (rowB[p] & 7)) * 16));
#pragma unroll
            for (int t = 0; t < 4; ++t)
#pragma unroll
                for (int u = 0; u < 4; ++u) {
                    int p = u >> 1, h = u & 1;
                    mma16816(acc[t][u], a[t], b[p][h], b[p][2 + h]);
                }
        }
    }

#pragma unroll
    for (int t = 0; t < 4; ++t) {
        int r = bm + wm + t * 16 + g4;
#pragma unroll
        for (int u = 0; u < 4; ++u) {
            int c = bn + wn + u * 8 + tg * 2;
            float b0 = 0.0f, b1 = 0.0f;
            if (bias) { b0 = bias[c]; b1 = bias[c + 1]; }
            *(__half2*)&Ch[(size_t)r * N + c] =
                __floats2half2_rn(acc[t][u][0] + b0, acc[t][u][1] + b1);
            *(__half2*)&Ch[(size_t)(r + 8) * N + c] =
                __floats2half2_rn(acc[t][u][2] + b0, acc[t][u][3] + b1);
        }
    }
}

// ------ kkt2+solve fused: grid BH, 512 threads (2 warpgroups), dyn smem -------
// wg g covers i in [g*512, g*512+512). Reduce in smem f32, then GJ solve +
// column softmax -> g_amap.
#define KS_HS(g)  ((g) * 27648)
#define KS_TS(g)  ((g) * 27648 + 9216)
#define KS_AF     55296
#define KS_XF     (55296 + 16640)
#define KS_SMEM   88576

__global__ __launch_bounds__(512) void kkt2_solve_kernel(
    const float* __restrict__ alpha_p, const float* __restrict__ temp_p)
{
    extern __shared__ char dyn[];
    int tid = threadIdx.x;
    int wg = tid >> 8;
    int gt = tid & 255;
    __half (*Hs)[72] = reinterpret_cast<__half (*)[72]>(dyn + KS_HS(wg));
    __half (*Tss)[72] = reinterpret_cast<__half (*)[72]>(dyn + KS_TS(wg));
    float (*Af)[65] = reinterpret_cast<float (*)[65]>(dyn + KS_AF);
    float (*Xf)[65] = reinterpret_cast<float (*)[65]>(dyn + KS_XF);
    const unsigned hb = (unsigned)__cvta_generic_to_shared(&Hs[0][0]);
    const unsigned tb = (unsigned)__cvta_generic_to_shared(&Tss[0][0]);

    int bh = blockIdx.x;
    int b = bh >> 4, h = bh & 15;
    const __half* hk = g_hk    + (size_t)b * DIM * DIM + (size_t)(h * HD) * DIM;
    const __half* wk = g_wh[1] + (size_t)(h * HD) * DIM;
    const __half* wv = g_wh[2] + (size_t)(h * HD) * DIM;

    const int lane = gt & 31;
    const int warp = gt >> 5;
    const int wm = (warp >> 2) * 32;
    const int wn = (warp & 3) * 32;
    const int g4 = lane >> 2;
    const int tg = lane & 3;

    float acc[2][4][4];
#pragma unroll
    for (int mt = 0; mt < 2; ++mt)
#pragma unroll
        for (int u = 0; u < 4; ++u)
#pragma unroll
            for (int r = 0; r < 4; ++r) acc[mt][u][r] = 0.0f;

    const int khalf = lane >> 4;
    int rowA[2], rowB[2];
#pragma unroll
    for (int mt = 0; mt < 2; ++mt) rowA[mt] = wm + mt * 16 + (lane & 15);
#pragma unroll
    for (int p = 0; p < 2; ++p) rowB[p] = wn + p * 16 + (lane & 15);

    for (int rr = 0; rr < 8; ++rr) {
        int i0 = wg * 512 + rr * 64;
        __syncthreads();
#pragma unroll
        for (int it = 0; it < 2; ++it) {
            int idx = gt + it * 256;
            int r = idx >> 3, c8 = (idx & 7) * 8;
            *(uint4*)&Hs[r][c8] = *(const uint4*)(hk + (size_t)r * DIM + i0 + c8);
        }
#pragma unroll
        for (int it = 0; it < 4; ++it) {
            int idx = gt + it * 256;
            int r = idx >> 3, c8 = (idx & 7) * 8;
            const __half* src = (r < 64 ? wk + (size_t)r * DIM
                                        : wv + (size_t)(r - 64) * DIM) + i0 + c8;
            *(uint4*)&Tss[r][c8] = *(const uint4*)src;
        }
        __syncthreads();

#pragma unroll
        for (int ks = 0; ks < 4; ++ks) {
            unsigned a[2][4], bfr[2][4];
            unsigned colb = (unsigned)(ks * 32 + khalf * 16);
#pragma unroll
            for (int mt = 0; mt < 2; ++mt)
                ldsm4(a[mt], hb + rowA[mt] * 144 + colb);
#pragma unroll
            for (int p = 0; p < 2; ++p)
                ldsm4(bfr[p], tb + rowB[p] * 144 + colb);
#pragma unroll
            for (int mt = 0; mt < 2; ++mt)
#pragma unroll
                for (int u = 0; u < 4; ++u) {
                    int p = u >> 1, hh = u & 1;
                    mma16816(acc[mt][u], a[mt], bfr[p][hh], bfr[p][2 + hh]);
                }
        }
    }

    // reduce the two warpgroups' accumulators into Af (kk) / Xf (kv)
    __syncthreads();
#pragma unroll
    for (int g = 0; g < 2; ++g) {
        if (wg == g) {
#pragma unroll
            for (int mt = 0; mt < 2; ++mt) {
                int d = wm + mt * 16 + g4;
#pragma unroll
                for (int u = 0; u < 4; ++u) {
                    int j = wn + u * 8 + tg * 2;
                    float* r0 = (j < 64) ? &Af[d][j] : &Xf[d][j - 64];
                    float* r1 = (j < 64) ? &Af[d + 8][j] : &Xf[d + 8][j - 64];
                    if (g == 0) {
                        r0[0] = acc[mt][u][0]; r0[1] = acc[mt][u][1];
                        r1[0] = acc[mt][u][2]; r1[1] = acc[mt][u][3];
                    } else {
                        r0[0] += acc[mt][u][0]; r0[1] += acc[mt][u][1];
                        r1[0] += acc[mt][u][2]; r1[1] += acc[mt][u][3];
                    }
                }
            }
        }
        __syncthreads();
    }

    if (tid < 64) Af[tid][tid] += alpha_p[0];

    int r  = tid >> 2;                 // 0..127 (r>=64 idle in updates)
    int c0 = (tid & 3) * 16;
    for (int pp = 0; pp < 64; ++pp) {
        __syncthreads();
        float pinv = 1.0f / Af[pp][pp];
        __syncthreads();
        if (tid < 64)       Af[pp][tid]      *= pinv;
        else if (tid < 128) Xf[pp][tid - 64] *= pinv;
        __syncthreads();
        float f = (r < 64 && r != pp) ? Af[r][pp] : 0.0f;
        __syncthreads();
        if (r < 64 && r != pp) {
#pragma unroll
            for (int c = 0; c < 16; ++c) {
                Af[r][c0 + c] = fmaf(-f, Af[pp][c0 + c], Af[r][c0 + c]);
                Xf[r][c0 + c] = fmaf(-f, Xf[pp][c0 + c], Xf[r][c0 + c]);
            }
        }
    }
    __syncthreads();

    if (tid < 64) {
        float invt = 1.0f / temp_p[0];
        float mx = -1e30f;
        for (int d = 0; d < 64; ++d) mx = fmaxf(mx, Xf[d][tid] * invt);
        float s = 0.0f;
        for (int d = 0; d < 64; ++d) s += expf(Xf[d][tid] * invt - mx);
        float inv_s = 1.0f / s;
        for (int d = 0; d < 64; ++d)
            g_amap[(size_t)bh * 4096 + d * 64 + tid] =
                expf(Xf[d][tid] * invt - mx) * inv_s;
    }
}

// ---------- fold1: W'_b[din, h*64+j] = sum_e Wq[h*64+e, din] * amap[e, j] -----
__global__ __launch_bounds__(256) void fold1_kernel()
{
    int bh = blockIdx.x;
    int chunk = blockIdx.y;
    int b = bh >> 4, h = bh & 15;

    __shared__ __half WqS[64][256];
    __shared__ float  AmS[64][64];
    int tid = threadIdx.x;

    const __half* wq = g_wh[0] + (size_t)(h * 64) * DIM + chunk * 256;
#pragma unroll
    for (int it = 0; it < 8; ++it) {
        int idx = tid + it * 256;
        int e = idx >> 5;
        int c8 = (idx & 31) * 8;
        *(uint4*)&WqS[e][c8] = *(const uint4*)(wq + (size_t)e * DIM + c8);
    }
#pragma unroll
    for (int it = 0; it < 4; ++it) {
        int idx = tid + it * 256;
        int e = idx >> 4;
        int j4 = (idx & 15) * 4;
        *(float4*)&AmS[e][j4] =
            *(const float4*)&g_amap[(size_t)bh * 4096 + e * 64 + j4];
    }
    __syncthreads();

    int ty = tid >> 3;
    int tx = tid & 7;
    float acc[8][8];
#pragma unroll
    for (int i = 0; i < 8; ++i)
#pragma unroll
        for (int j = 0; j < 8; ++j) acc[i][j] = 0.0f;

#pragma unroll 4
    for (int e = 0; e < 64; ++e) {
        __half ah[8];
        *(uint4*)ah = *(const uint4*)&WqS[e][ty * 8];
        float bv[8];
        float4 b0 = *(const float4*)&AmS[e][tx * 8];
        float4 b1 = *(const float4*)&AmS[e][tx * 8 + 4];
        bv[0]=b0.x; bv[1]=b0.y; bv[2]=b0.z; bv[3]=b0.w;
        bv[4]=b1.x; bv[5]=b1.y; bv[6]=b1.z; bv[7]=b1.w;
#pragma unroll
        for (int i = 0; i < 8; ++i) {
            float av = __half2float(ah[i]);
#pragma unroll
            for (int j = 0; j < 8; ++j) acc[i][j] = fmaf(av, bv[j], acc[i][j]);
        }
    }

    __half* wp = g_wp + (size_t)b * DIM * DIM;
#pragma unroll
    for (int i = 0; i < 8; ++i) {
        int din = chunk * 256 + ty * 8 + i;
        __half o[8];
#pragma unroll
        for (int j = 0; j < 8; ++j) o[j] = __float2half_rn(acc[i][j]);
        *(uint4*)&wp[(size_t)din * DIM + h * 64 + tx * 8] = *(const uint4*)o;
    }
}

// ---------------- LayerNorm(proj(fp16) + x(f32)), warp-per-row ----------------
__global__ __launch_bounds__(256) void ln_kernel(
    const float* __restrict__ x, const float* __restrict__ gamma,
    const float* __restrict__ beta, float* __restrict__ out)
{
    int wid = threadIdx.x >> 5;
    int lane = threadIdx.x & 31;
    int row = blockIdx.x * 8 + wid;
    const __half* pr = g_projh + (size_t)row * DIM;
    const float*  xr = x       + (size_t)row * DIM;

    float v[32];
    float s = 0.0f, s2 = 0.0f;
#pragma unroll
    for (int c = 0; c < 8; ++c) {
        int base = c * 128 + lane * 4;
        uint2 pu = *(const uint2*)(pr + base);
        __half2 p0 = *reinterpret_cast<__half2*>(&pu.x);
        __half2 p1 = *reinterpret_cast<__half2*>(&pu.y);
        float4 xv = *(const float4*)(xr + base);
        float* vc = v + c * 4;
        vc[0] = __low2float(p0) + xv.x;
        vc[1] = __high2float(p0) + xv.y;
        vc[2] = __low2float(p1) + xv.z;
        vc[3] = __high2float(p1) + xv.w;
#pragma unroll
        for (int k = 0; k < 4; ++k) { s += vc[k]; s2 += vc[k] * vc[k]; }
    }

#pragma unroll
    for (int o = 16; o > 0; o >>= 1) {
        s  += __shfl_xor_sync(0xFFFFFFFFu, s,  o);
        s2 += __shfl_xor_sync(0xFFFFFFFFu, s2, o);
    }
    float mu  = s  * (1.0f / DIM);
    float var = s2 * (1.0f / DIM) - mu * mu;
    float rstd = rsqrtf(var + LNEPS);

#pragma unroll
    for (int c = 0; c < 8; ++c) {
        int base = c * 128 + lane * 4;
        float4 gp = *(const float4*)(gamma + base);
        float4 bp = *(const float4*)(beta  + base);
        float* vc = v + c * 4;
        float4 o4;
        o4.x = (vc[0] - mu) * rstd * gp.x + bp.x;
        o4.y = (vc[1] - mu) * rstd * gp.y + bp.y;
        o4.z = (vc[2] - mu) * rstd * gp.z + bp.z;
        o4.w = (vc[3] - mu) * rstd * gp.w + bp.w;
        *(float4*)(out + (size_t)row * DIM + base) = o4;
    }
}

// ---------------- host launcher ----------------------------------------------
extern "C" void kernel_launch(void* const* d_in, const int* in_sizes, int n_in,
                              void* d_out, int out_size)
{
    (void)in_sizes; (void)n_in; (void)out_size;
    const float* x     = (const float*)d_in[0];
    const float* Wq    = (const float*)d_in[1];
    const float* Wk    = (const float*)d_in[2];
    const float* Wv    = (const float*)d_in[3];
    const float* Wo    = (const float*)d_in[4];
    const float* bo    = (const float*)d_in[5];
    const float* alpha = (const float*)d_in[6];
    const float* temp  = (const float*)d_in[7];
    const float* gamma = (const float*)d_in[8];
    const float* beta  = (const float*)d_in[9];
    float* out = (float*)d_out;

    __half *xh, *wh, *gm, *hk, *wpp, *w2p, *projh;
    cudaGetSymbolAddress((void**)&xh,    g_xh);
    cudaGetSymbolAddress((void**)&wh,    g_wh);
    cudaGetSymbolAddress((void**)&gm,    g_gm);
    cudaGetSymbolAddress((void**)&hk,    g_hk);
    cudaGetSymbolAddress((void**)&wpp,   g_wp);
    cudaGetSymbolAddress((void**)&w2p,   g_w2);
    cudaGetSymbolAddress((void**)&projh, g_projh);

    const int SMEM_GEMM = 98304;
    cudaFuncSetAttribute(gemm_f16,
                         cudaFuncAttributeMaxDynamicSharedMemorySize, SMEM_GEMM);
    cudaFuncSetAttribute(gsplit_kernel,
                         cudaFuncAttributeMaxDynamicSharedMemorySize, SMEM_GEMM);
    cudaFuncSetAttribute(kkt2_solve_kernel,
                         cudaFuncAttributeMaxDynamicSharedMemorySize, KS_SMEM);

    const size_t WSZ = (size_t)DIM * DIM;

    // fused conversions: x -> xh/xt and 4 weights -> fp16
    conv_all<<<dim3(DIM/64, SEQ/64, BATCH + 1), 256>>>(x, Wq, Wk, Wv, Wo);

    // G_b = X_b^T X_b: split-K=2 f32 partials on triangle, then reduce+mirror
    gsplit_kernel<<<dim3(36, 1, BATCH*2), 256, SMEM_GEMM>>>();
    greduce_kernel<<<dim3(72, 1, BATCH), 256>>>();

    // Hk_b = Wk @ G_b
    gemm_f16<<<dim3(DIM/128, DIM/128, BATCH), 256, SMEM_GEMM>>>(
        wh + 1*WSZ, gm, nullptr, hk, DIM, DIM/64, DIM, DIM, 0, WSZ, WSZ);

    // per-head Gram blocks + solve + softmax (fused)
    kkt2_solve_kernel<<<BH, 512, KS_SMEM>>>(alpha, temp);

    // fold amap into weights
    fold1_kernel<<<dim3(BH, DIM/256), 256>>>();
    gemm_f16<<<dim3(DIM/128, DIM/128, BATCH), 256, SMEM_GEMM>>>(
        wh + 3*WSZ, wpp, nullptr, w2p, DIM, DIM/64, DIM, DIM, 0, WSZ, WSZ);

    // proj[b] = x[b] @ W2_b + bo  (fp16 out)
    gemm_f16<<<dim3(DIM/128, SEQ/128, BATCH), 256, SMEM_GEMM>>>(
        xh, w2p, bo, projh, DIM, DIM/64, DIM, DIM,
        (size_t)SEQ*DIM, WSZ, (size_t)SEQ*DIM);

    ln_kernel<<<MTOT/8, 256>>>(x, gamma, beta, out);
}

// round 16
// speedup vs baseline: 1.4697x; 1.0060x over previous
#include <cuda_runtime.h>
#include <cuda_fp16.h>
#include <cstdint>
#include <math.h>

#define BATCH 4
#define SEQ   4096
#define DIM   1024
#define NH    16
#define HD    64
#define BH    (BATCH*NH)          // 64
#define MTOT  (BATCH*SEQ)         // 16384
#define LNEPS 1e-5f

// ---------------- scratch (static device globals; no allocation) -------------
__device__ __align__(16) __half g_xh [(size_t)MTOT*DIM];
__device__ __align__(16) __half g_xt [(size_t)BATCH*DIM*SEQ];   // X^T per batch
__device__ __align__(16) __half g_wh [4][(size_t)DIM*DIM];
__device__ __align__(16) float  g_gp [(size_t)BATCH*2*DIM*DIM]; // G split-K partials
__device__ __align__(16) __half g_gm [(size_t)BATCH*DIM*DIM];   // G = X^T X
__device__ __align__(16) __half g_hk [(size_t)BATCH*DIM*DIM];   // Hk = Wk G
__device__ __align__(16) __half g_wp [(size_t)BATCH*DIM*DIM];   // folded W'
__device__ __align__(16) __half g_w2 [(size_t)BATCH*DIM*DIM];   // folded W2^T
__device__ __align__(16) __half g_projh[(size_t)MTOT*DIM];
__device__ float g_amap[BH*HD*HD];

// ---------------- async copy / mma helpers ------------------------------------
#define CP16(dst_u32, src_ptr) \
    asm volatile("cp.async.cg.shared.global [%0], [%1], 16;\n" \
                 :: "r"(dst_u32), "l"(src_ptr))
#define CPCOMMIT() asm volatile("cp.async.commit_group;\n" ::: "memory")
#define CPWAIT1()  asm volatile("cp.async.wait_group 1;\n" ::: "memory")

__device__ __forceinline__ void ldsm4(unsigned r[4], unsigned addr) {
    asm volatile("ldmatrix.sync.aligned.m8n8.x4.shared.b16 {%0,%1,%2,%3}, [%4];"
                 : "=r"(r[0]), "=r"(r[1]), "=r"(r[2]), "=r"(r[3]) : "r"(addr));
}

__device__ __forceinline__ void mma16816(float* c, const unsigned a[4],
                                         unsigned b0, unsigned b1) {
    asm volatile(
        "mma.sync.aligned.m16n8k16.row.col.f32.f16.f16.f32 "
        "{%0,%1,%2,%3}, {%4,%5,%6,%7}, {%8,%9}, {%0,%1,%2,%3};"
        : "+f"(c[0]), "+f"(c[1]), "+f"(c[2]), "+f"(c[3])
        : "r"(a[0]), "r"(a[1]), "r"(a[2]), "r"(a[3]), "r"(b0), "r"(b1));
}

__device__ __forceinline__ void tri_idx(int t, int& I, int& J) {
    int acc = 0; I = 0;
    while (acc + I + 1 <= t) { acc += I + 1; ++I; }
    J = t - acc;
}

// ---- conv_all: z<BATCH -> x(f32)->xh+xt; z==BATCH -> 4 weights -> fp16 -------
__global__ __launch_bounds__(256) void conv_all(
    const float* __restrict__ x,
    const float* __restrict__ w0, const float* __restrict__ w1,
    const float* __restrict__ w2, const float* __restrict__ w3)
{
    int tid = threadIdx.x;
    if (blockIdx.z == BATCH) {
        const float* srcs[4] = { w0, w1, w2, w3 };
        int lb = blockIdx.y * 16 + blockIdx.x;      // 0..1023
#pragma unroll
        for (int it = 0; it < 2; ++it) {
            size_t idx = (size_t)lb * 4096 + it * 2048 + tid * 8;
            int wsel = (int)(idx >> 20);
            size_t off = idx & ((1u << 20) - 1);
            const float* src = srcs[wsel];
            float4 v0 = *(const float4*)(src + off);
            float4 v1 = *(const float4*)(src + off + 4);
            __half o[8];
            o[0] = __float2half_rn(v0.x); o[1] = __float2half_rn(v0.y);
            o[2] = __float2half_rn(v0.z); o[3] = __float2half_rn(v0.w);
            o[4] = __float2half_rn(v1.x); o[5] = __float2half_rn(v1.y);
            o[6] = __float2half_rn(v1.z); o[7] = __float2half_rn(v1.w);
            *(uint4*)(&g_wh[wsel][0] + off) = *(const uint4*)o;
        }
        return;
    }
    int ib = blockIdx.x, nb = blockIdx.y, b = blockIdx.z;
    __shared__ __half Ts[64][64];
    const float* src = x + ((size_t)(b * SEQ + nb * 64)) * DIM + ib * 64;
    __half* xh = g_xh + ((size_t)(b * SEQ + nb * 64)) * DIM + ib * 64;
#pragma unroll
    for (int it = 0; it < 2; ++it) {
        int idx = tid + it * 256;
        int r  = idx >> 3;
        int cc = idx & 7;
        float4 v0 = *(const float4*)(src + (size_t)r * DIM + cc * 8);
        float4 v1 = *(const float4*)(src + (size_t)r * DIM + cc * 8 + 4);
        __half o[8];
        o[0] = __float2half_rn(v0.x); o[1] = __float2half_rn(v0.y);
        o[2] = __float2half_rn(v0.z); o[3] = __float2half_rn(v0.w);
        o[4] = __float2half_rn(v1.x); o[5] = __float2half_rn(v1.y);
        o[6] = __float2half_rn(v1.z); o[7] = __float2half_rn(v1.w);
        *(uint4*)(xh + (size_t)r * DIM + cc * 8) = *(const uint4*)o;
        int ccs = cc ^ ((r >> 3) & 7);
        *(uint4*)&Ts[r][ccs * 8] = *(const uint4*)o;
    }
    __syncthreads();
    __half* dst = g_xt + ((size_t)b * DIM + ib * 64) * SEQ + nb * 64;
#pragma unroll
    for (int it = 0; it < 2; ++it) {
        int idx = tid + it * 256;
        int ng = idx & 7;
        int i  = idx >> 3;
        __half o[8];
#pragma unroll
        for (int k = 0; k < 8; ++k) {
            int n = ng * 8 + k;
            int cc = (i >> 3) ^ ((n >> 3) & 7);
            o[k] = Ts[n][cc * 8 + (i & 7)];
        }
        *(uint4*)(dst + (size_t)i * SEQ + ng * 8) = *(const uint4*)o;
    }
}

// ------------- G split-K GEMM: triangle-indexed tiles, f32 partial out --------
__global__ __launch_bounds__(256) void gsplit_kernel()
{
    extern __shared__ __half sm[];
    const unsigned smem_base = (unsigned)__cvta_generic_to_shared(sm);
    const int tid  = threadIdx.x;
    const int lane = tid & 31;
    const int warp = tid >> 5;
    const int wm = (warp >> 2) * 64;
    const int wn = (warp & 3) * 32;
    int I, J;
    tri_idx(blockIdx.x, I, J);
    const int bm = I * 128;
    const int bn = J * 128;
    const int b = blockIdx.z >> 1;
    const int sp = blockIdx.z & 1;
    const int g4 = lane >> 2;
    const int tg = lane & 3;

    const __half* A2 = g_xt + (size_t)b * DIM * SEQ;
    float* Cf = g_gp + (size_t)blockIdx.z * DIM * DIM;

    float acc[4][4][4];
#pragma unroll
    for (int t = 0; t < 4; ++t)
#pragma unroll
        for (int u = 0; u < 4; ++u)
#pragma unroll
            for (int r = 0; r < 4; ++r) acc[t][u][r] = 0.0f;

    auto load_chunk = [&](int kc, int bf) {
#pragma unroll
        for (int it = 0; it < 4; ++it) {
            int idx = tid + it * 256;
            int row = idx >> 3;
            int c8  = idx & 7;
            const __half* sa = A2 + (size_t)(bm + row) * SEQ + kc * 64 + c8 * 8;
            const __half* sb = A2 + (size_t)(bn + row) * SEQ + kc * 64 + c8 * 8;
            unsigned sw = (unsigned)((c8 ^ (row & 7)) * 16);
            CP16(smem_base + bf * 16384 + row * 128 + sw, sa);
            CP16(smem_base + 49152 + bf * 16384 + row * 128 + sw, sb);
        }
    };

    const int khalf = lane >> 4;
    int rowA[4], rowB[2];
#pragma unroll
    for (int t = 0; t < 4; ++t) rowA[t] = wm + t * 16 + (lane & 15);
#pragma unroll
    for (int p = 0; p < 2; ++p) rowB[p] = wn + p * 16 + (lane & 15);

    const int k0 = sp * 32;
    load_chunk(k0 + 0, 0); CPCOMMIT();
    load_chunk(k0 + 1, 1); CPCOMMIT();

    for (int kc = 0; kc < 32; ++kc) {
        CPWAIT1();
        __syncthreads();
        if (kc + 2 < 32) { load_chunk(k0 + kc + 2, (kc + 2) % 3); CPCOMMIT(); }

        const int bf = kc % 3;
        const unsigned abase = smem_base + bf * 16384;
        const unsigned bbase = smem_base + 49152 + bf * 16384;

#pragma unroll
        for (int s = 0; s < 4; ++s) {
            const int ch = s * 2 + khalf;
            unsigned a[4][4], bfr[2][4];
#pragma unroll
            for (int t = 0; t < 4; ++t)
                ldsm4(a[t], abase + rowA[t] * 128 +
                             (unsigned)((ch ^ (rowA[t] & 7)) * 16));
#pragma unroll
            for (int p = 0; p < 2; ++p)
                ldsm4(bfr[p], bbase + rowB[p] * 128 +
                              (unsigned)((ch ^ (rowB[p] & 7)) * 16));
#pragma unroll
            for (int t = 0; t < 4; ++t)
#pragma unroll
                for (int u = 0; u < 4; ++u) {
                    int p = u >> 1, h = u & 1;
                    mma16816(acc[t][u], a[t], bfr[p][h], bfr[p][2 + h]);
                }
        }
    }

#pragma unroll
    for (int t = 0; t < 4; ++t) {
        int r = bm + wm + t * 16 + g4;
#pragma unroll
        for (int u = 0; u < 4; ++u) {
            int c = bn + wn + u * 8 + tg * 2;
            *(float2*)&Cf[(size_t)r * DIM + c] =
                make_float2(acc[t][u][0], acc[t][u][1]);
            *(float2*)&Cf[(size_t)(r + 8) * DIM + c] =
                make_float2(acc[t][u][2], acc[t][u][3]);
        }
    }
}

// ------------- greduce: sum 2 partials -> fp16 G + mirror; half-tiles ---------
__global__ __launch_bounds__(256) void greduce_kernel()
{
    int I, J;
    tri_idx(blockIdx.x >> 1, I, J);
    int half = blockIdx.x & 1;
    int bm = I * 128, bn = J * 128;
    int b = blockIdx.z;
    int tid = threadIdx.x;
    __shared__ __half S[64][132];

    const float* p0 = g_gp + (size_t)(b * 2 + 0) * DIM * DIM;
    const float* p1 = g_gp + (size_t)(b * 2 + 1) * DIM * DIM;
    __half* Gm = g_gm + (size_t)b * DIM * DIM;
    int rbase = bm + half * 64;

#pragma unroll
    for (int it = 0; it < 8; ++it) {
        int idx = tid + it * 256;
        int r  = idx >> 5;
        int c4 = (idx & 31) * 4;
        size_t off = (size_t)(rbase + r) * DIM + bn + c4;
        float4 a = *(const float4*)(p0 + off);
        float4 c = *(const float4*)(p1 + off);
        __half2 h0 = __floats2half2_rn(a.x + c.x, a.y + c.y);
        __half2 h1 = __floats2half2_rn(a.z + c.z, a.w + c.w);
        __half o[4];
        *(__half2*)&o[0] = h0;
        *(__half2*)&o[2] = h1;
        *(uint2*)&Gm[off] = *(const uint2*)o;
        *(__half2*)&S[r][c4]     = h0;
        *(__half2*)&S[r][c4 + 2] = h1;
    }

    if (bn < bm) {
        __syncthreads();
#pragma unroll
        for (int it = 0; it < 4; ++it) {
            int idx = tid + it * 256;
            int j  = idx >> 3;
            int i0 = (idx & 7) * 8;
            __half o[8];
#pragma unroll
            for (int k = 0; k < 8; ++k) o[k] = S[i0 + k][j];
            *(uint4*)&Gm[(size_t)(bn + j) * DIM + rbase + i0] = *(const uint4*)o;
        }
    }
}

// ---------------- fp16 GEMM 128x128 tile (multi-wave shapes) ------------------
__global__ __launch_bounds__(256) void gemm_f16(
    const __half* __restrict__ A0, const __half* __restrict__ B0,
    const float* __restrict__ bias, __half* __restrict__ Ch0, int N,
    int nck, int lda, int ldb, size_t strA, size_t strB, size_t strC)
{
    extern __shared__ __half sm[];
    const unsigned smem_base = (unsigned)__cvta_generic_to_shared(sm);
    const int tid  = threadIdx.x;
    const int lane = tid & 31;
    const int warp = tid >> 5;
    const int wm = (warp >> 2) * 64;
    const int wn = (warp & 3) * 32;
    const int bm = blockIdx.y * 128;
    const int bn = blockIdx.x * 128;
    const int z  = blockIdx.z;
    const int g4 = lane >> 2;
    const int tg = lane & 3;

    const __half* A2 = A0 + (size_t)z * strA;
    const __half* B2 = B0 + (size_t)z * strB;
    __half* Ch = Ch0 + (size_t)z * strC;

    float acc[4][4][4];
#pragma unroll
    for (int t = 0; t < 4; ++t)
#pragma unroll
        for (int u = 0; u < 4; ++u)
#pragma unroll
            for (int r = 0; r < 4; ++r) acc[t][u][r] = 0.0f;

    auto load_chunk = [&](int kc, int bf) {
#pragma unroll
        for (int it = 0; it < 4; ++it) {
            int idx = tid + it * 256;
            int row = idx >> 3;
            int c8  = idx & 7;
            const __half* sa = A2 + (size_t)(bm + row) * lda + kc * 64 + c8 * 8;
            const __half* sb = B2 + (size_t)(bn + row) * ldb + kc * 64 + c8 * 8;
            unsigned sw = (unsigned)((c8 ^ (row & 7)) * 16);
            CP16(smem_base + bf * 16384 + row * 128 + sw, sa);
            CP16(smem_base + 49152 + bf * 16384 + row * 128 + sw, sb);
        }
    };

    const int khalf = lane >> 4;
    int rowA[4], rowB[2];
#pragma unroll
    for (int t = 0; t < 4; ++t) rowA[t] = wm + t * 16 + (lane & 15);
#pragma unroll
    for (int p = 0; p < 2; ++p) rowB[p] = wn + p * 16 + (lane & 15);

    load_chunk(0, 0); CPCOMMIT();
    load_chunk(1, 1); CPCOMMIT();

    for (int kc = 0; kc < nck; ++kc) {
        CPWAIT1();
        __syncthreads();
        if (kc + 2 < nck) { load_chunk(kc + 2, (kc + 2) % 3); CPCOMMIT(); }

        const int bf = kc % 3;
        const unsigned abase = smem_base + bf * 16384;
        const unsigned bbase = smem_base + 49152 + bf * 16384;

#pragma unroll
        for (int s = 0; s < 4; ++s) {
            const int ch = s * 2 + khalf;
            unsigned a[4][4], b[2][4];
#pragma unroll
            for (int t = 0; t < 4; ++t)
                ldsm4(a[t], abase + rowA[t] * 128 +
                             (unsigned)((ch ^ (rowA[t] & 7)) * 16));
#pragma unroll
            for (int p = 0; p < 2; ++p)
                ldsm4(b[p], bbase + rowB[p] * 128 +
                             (unsigned)((ch ^ (rowB[p] & 7)) * 16));
#pragma unroll
            for (int t = 0; t < 4; ++t)
#pragma unroll
                for (int u = 0; u < 4; ++u) {
                    int p = u >> 1, h = u & 1;
                    mma16816(acc[t][u], a[t], b[p][h], b[p][2 + h]);
                }
        }
    }

#pragma unroll
    for (int t = 0; t < 4; ++t) {
        int r = bm + wm + t * 16 + g4;
#pragma unroll
        for (int u = 0; u < 4; ++u) {
            int c = bn + wn + u * 8 + tg * 2;
            float b0 = 0.0f, b1 = 0.0f;
            if (bias) { b0 = bias[c]; b1 = bias[c + 1]; }
            *(__half2*)&Ch[(size_t)r * N + c] =
                __floats2half2_rn(acc[t][u][0] + b0, acc[t][u][1] + b1);
            *(__half2*)&Ch[(size_t)(r + 8) * N + c] =
                __floats2half2_rn(acc[t][u][2] + b0, acc[t][u][3] + b1);
        }
    }
}

// -------- wide fp16 GEMM: 128x256 tile, 1 CTA/SM, for square batched GEMMs ----
// 8 warps at 64x64 warp tile. smem: A 3x16KB @0, B 3x32KB @49152 (stride 32768!)
__global__ __launch_bounds__(256, 1) void gemm_wide(
    const __half* __restrict__ A0, const __half* __restrict__ B0,
    __half* __restrict__ Ch0, int N,
    int nck, int lda, int ldb, size_t strA, size_t strB, size_t strC)
{
    extern __shared__ __half sm[];
    const unsigned smem_base = (unsigned)__cvta_generic_to_shared(sm);
    const int tid  = threadIdx.x;
    const int lane = tid & 31;
    const int warp = tid >> 5;
    const int wm = (warp >> 2) * 64;     // 2 warps M
    const int wn = (warp & 3) * 64;      // 4 warps N
    const int bm = blockIdx.y * 128;
    const int bn = blockIdx.x * 256;
    const int z  = blockIdx.z;
    const int g4 = lane >> 2;
    const int tg = lane & 3;

    const __half* A2 = A0 + (size_t)z * strA;
    const __half* B2 = B0 + (size_t)z * strB;
    __half* Ch = Ch0 + (size_t)z * strC;

    float acc[4][8][4];
#pragma unroll
    for (int t = 0; t < 4; ++t)
#pragma unroll
        for (int u = 0; u < 8; ++u)
#pragma unroll
            for (int r = 0; r < 4; ++r) acc[t][u][r] = 0.0f;

    auto load_chunk = [&](int kc, int bf) {
#pragma unroll
        for (int it = 0; it < 4; ++it) {          // A: 128 rows x 8 c8
            int idx = tid + it * 256;
            int row = idx >> 3;
            int c8  = idx & 7;
            const __half* sa = A2 + (size_t)(bm + row) * lda + kc * 64 + c8 * 8;
            unsigned sw = (unsigned)((c8 ^ (row & 7)) * 16);
            CP16(smem_base + bf * 16384 + row * 128 + sw, sa);
        }
#pragma unroll
        for (int it = 0; it < 8; ++it) {          // B: 256 rows x 8 c8
            int idx = tid + it * 256;
            int row = idx >> 3;
            int c8  = idx & 7;
            const __half* sb = B2 + (size_t)(bn + row) * ldb + kc * 64 + c8 * 8;
            unsigned sw = (unsigned)((c8 ^ (row & 7)) * 16);
            CP16(smem_base + 49152 + bf * 32768 + row * 128 + sw, sb);
        }
    };

    const int khalf = lane >> 4;
    int rowA[4], rowB[4];
#pragma unroll
    for (int t = 0; t < 4; ++t) rowA[t] = wm + t * 16 + (lane & 15);
#pragma unroll
    for (int p = 0; p < 4; ++p) rowB[p] = wn + p * 16 + (lane & 15);

    load_chunk(0, 0); CPCOMMIT();
    load_chunk(1, 1); CPCOMMIT();

    for (int kc = 0; kc < nck; ++kc) {
        CPWAIT1();
        __syncthreads();
        if (kc + 2 < nck) { load_chunk(kc + 2, (kc + 2) % 3); CPCOMMIT(); }

        const int bf = kc % 3;
        const unsigned abase = smem_base + bf * 16384;
        const unsigned bbase = smem_base + 49152 + bf * 32768;

#pragma unroll
        for (int s = 0; s < 4; ++s) {
            const int ch = s * 2 + khalf;
            unsigned a[4][4], b[4][4];
#pragma unroll
            for (int t = 0; t < 4; ++t)
                ldsm4(a[t], abase + rowA[t] * 128 +
                             (unsigned)((ch ^ (rowA[t] & 7)) * 16));
#pragma unroll
            for (int p = 0; p < 4; ++p)
                ldsm4(b[p], bbase + rowB[p] * 128 +
                             (unsigned)((ch ^ (rowB[p] & 7)) * 16));
#pragma unroll
            for (int t = 0; t < 4; ++t)
#pragma unroll
                for (int u = 0; u < 8; ++u) {
                    int p = u >> 1, h = u & 1;
                    mma16816(acc[t][u], a[t], b[p][h], b[p][2 + h]);
                }
        }
    }

#pragma unroll
    for (int t = 0; t < 4; ++t) {
        int r = bm + wm + t * 16 + g4;
#pragma unroll
        for (int u = 0; u < 8; ++u) {
            int c = bn + wn + u * 8 + tg * 2;
            *(__half2*)&Ch[(size_t)r * N + c] =
                __floats2half2_rn(acc[t][u][0], acc[t][u][1]);
            *(__half2*)&Ch[(size_t)(r + 8) * N + c] =
                __floats2half2_rn(acc[t][u][2], acc[t][u][3]);
        }
    }
}

// ------ kkt2+solve fused: grid BH, 512 threads (2 warpgroups), dyn smem -------
#define KS_HS(g)  ((g) * 27648)
#define KS_TS(g)  ((g) * 27648 + 9216)
#define KS_AF     55296
#define KS_XF     (55296 + 16640)
#define KS_SMEM   88576

__global__ __launch_bounds__(512) void kkt2_solve_kernel(
    const float* __restrict__ alpha_p, const float* __restrict__ temp_p)
{
    extern __shared__ char dyn[];
    int tid = threadIdx.x;
    int wg = tid >> 8;
    int gt = tid & 255;
    __half (*Hs)[72] = reinterpret_cast<__half (*)[72]>(dyn + KS_HS(wg));
    __half (*Tss)[72] = reinterpret_cast<__half (*)[72]>(dyn + KS_TS(wg));
    float (*Af)[65] = reinterpret_cast<float (*)[65]>(dyn + KS_AF);
    float (*Xf)[65] = reinterpret_cast<float (*)[65]>(dyn + KS_XF);
    const unsigned hb = (unsigned)__cvta_generic_to_shared(&Hs[0][0]);
    const unsigned tb = (unsigned)__cvta_generic_to_shared(&Tss[0][0]);

    int bh = blockIdx.x;
    int b = bh >> 4, h = bh & 15;
    const __half* hk = g_hk    + (size_t)b * DIM * DIM + (size_t)(h * HD) * DIM;
    const __half* wk = g_wh[1] + (size_t)(h * HD) * DIM;
    const __half* wv = g_wh[2] + (size_t)(h * HD) * DIM;

    const int lane = gt & 31;
    const int warp = gt >> 5;
    const int wm = (warp >> 2) * 32;
    const int wn = (warp & 3) * 32;
    const int g4 = lane >> 2;
    const int tg = lane & 3;

    float acc[2][4][4];
#pragma unroll
    for (int mt = 0; mt < 2; ++mt)
#pragma unroll
        for (int u = 0; u < 4; ++u)
#pragma unroll
            for (int r = 0; r < 4; ++r) acc[mt][u][r] = 0.0f;

    const int khalf = lane >> 4;
    int rowA[2], rowB[2];
#pragma unroll
    for (int mt = 0; mt < 2; ++mt) rowA[mt] = wm + mt * 16 + (lane & 15);
#pragma unroll
    for (int p = 0; p < 2; ++p) rowB[p] = wn + p * 16 + (lane & 15);

    for (int rr = 0; rr < 8; ++rr) {
        int i0 = wg * 512 + rr * 64;
        __syncthreads();
#pragma unroll
        for (int it = 0; it < 2; ++it) {
            int idx = gt + it * 256;
            int r = idx >> 3, c8 = (idx & 7) * 8;
            *(uint4*)&Hs[r][c8] = *(const uint4*)(hk + (size_t)r * DIM + i0 + c8);
        }
#pragma unroll
        for (int it = 0; it < 4; ++it) {
            int idx = gt + it * 256;
            int r = idx >> 3, c8 = (idx & 7) * 8;
            const __half* src = (r < 64 ? wk + (size_t)r * DIM
                                        : wv + (size_t)(r - 64) * DIM) + i0 + c8;
            *(uint4*)&Tss[r][c8] = *(const uint4*)src;
        }
        __syncthreads();

#pragma unroll
        for (int ks = 0; ks < 4; ++ks) {
            unsigned a[2][4], bfr[2][4];
            unsigned colb = (unsigned)(ks * 32 + khalf * 16);
#pragma unroll
            for (int mt = 0; mt < 2; ++mt)
                ldsm4(a[mt], hb + rowA[mt] * 144 + colb);
#pragma unroll
            for (int p = 0; p < 2; ++p)
                ldsm4(bfr[p], tb + rowB[p] * 144 + colb);
#pragma unroll
            for (int mt = 0; mt < 2; ++mt)
#pragma unroll
                for (int u = 0; u < 4; ++u) {
                    int p = u >> 1, hh = u & 1;
                    mma16816(acc[mt][u], a[mt], bfr[p][hh], bfr[p][2 + hh]);
                }
        }
    }

    __syncthreads();
#pragma unroll
    for (int g = 0; g < 2; ++g) {
        if (wg == g) {
#pragma unroll
            for (int mt = 0; mt < 2; ++mt) {
                int d = wm + mt * 16 + g4;
#pragma unroll
                for (int u = 0; u < 4; ++u) {
                    int j = wn + u * 8 + tg * 2;
                    float* r0 = (j < 64) ? &Af[d][j] : &Xf[d][j - 64];
                    float* r1 = (j < 64) ? &Af[d + 8][j] : &Xf[d + 8][j - 64];
                    if (g == 0) {
                        r0[0] = acc[mt][u][0]; r0[1] = acc[mt][u][1];
                        r1[0] = acc[mt][u][2]; r1[1] = acc[mt][u][3];
                    } else {
                        r0[0] += acc[mt][u][0]; r0[1] += acc[mt][u][1];
                        r1[0] += acc[mt][u][2]; r1[1] += acc[mt][u][3];
                    }
                }
            }
        }
        __syncthreads();
    }

    if (tid < 64) Af[tid][tid] += alpha_p[0];

    int r  = tid >> 2;
    int c0 = (tid & 3) * 16;
    for (int pp = 0; pp < 64; ++pp) {
        __syncthreads();
        float pinv = 1.0f / Af[pp][pp];
        __syncthreads();
        if (tid < 64)       Af[pp][tid]      *= pinv;
        else if (tid < 128) Xf[pp][tid - 64] *= pinv;
        __syncthreads();
        float f = (r < 64 && r != pp) ? Af[r][pp] : 0.0f;
        __syncthreads();
        if (r < 64 && r != pp) {
#pragma unroll
            for (int c = 0; c < 16; ++c) {
                Af[r][c0 + c] = fmaf(-f, Af[pp][c0 + c], Af[r][c0 + c]);
                Xf[r][c0 + c] = fmaf(-f, Xf[pp][c0 + c], Xf[r][c0 + c]);
            }
        }
    }
    __syncthreads();

    if (tid < 64) {
        float invt = 1.0f / temp_p[0];
        float mx = -1e30f;
        for (int d = 0; d < 64; ++d) mx = fmaxf(mx, Xf[d][tid] * invt);
        float s = 0.0f;
        for (int d = 0; d < 64; ++d) s += expf(Xf[d][tid] * invt - mx);
        float inv_s = 1.0f / s;
        for (int d = 0; d < 64; ++d)
            g_amap[(size_t)bh * 4096 + d * 64 + tid] =
                expf(Xf[d][tid] * invt - mx) * inv_s;
    }
}

// ---------- fold1: W'_b[din, h*64+j] = sum_e Wq[h*64+e, din] * amap[e, j] -----
__global__ __launch_bounds__(256) void fold1_kernel()
{
    int bh = blockIdx.x;
    int chunk = blockIdx.y;
    int b = bh >> 4, h = bh & 15;

    __shared__ __half WqS[64][256];
    __shared__ float  AmS[64][64];
    int tid = threadIdx.x;

    const __half* wq = g_wh[0] + (size_t)(h * 64) * DIM + chunk * 256;
#pragma unroll
    for (int it = 0; it < 8; ++it) {
        int idx = tid + it * 256;
        int e = idx >> 5;
        int c8 = (idx & 31) * 8;
        *(uint4*)&WqS[e][c8] = *(const uint4*)(wq + (size_t)e * DIM + c8);
    }
#pragma unroll
    for (int it = 0; it < 4; ++it) {
        int idx = tid + it * 256;
        int e = idx >> 4;
        int j4 = (idx & 15) * 4;
        *(float4*)&AmS[e][j4] =
            *(const float4*)&g_amap[(size_t)bh * 4096 + e * 64 + j4];
    }
    __syncthreads();

    int ty = tid >> 3;
    int tx = tid & 7;
    float acc[8][8];
#pragma unroll
    for (int i = 0; i < 8; ++i)
#pragma unroll
        for (int j = 0; j < 8; ++j) acc[i][j] = 0.0f;

#pragma unroll 4
    for (int e = 0; e < 64; ++e) {
        __half ah[8];
        *(uint4*)ah = *(const uint4*)&WqS[e][ty * 8];
        float bv[8];
        float4 b0 = *(const float4*)&AmS[e][tx * 8];
        float4 b1 = *(const float4*)&AmS[e][tx * 8 + 4];
        bv[0]=b0.x; bv[1]=b0.y; bv[2]=b0.z; bv[3]=b0.w;
        bv[4]=b1.x; bv[5]=b1.y; bv[6]=b1.z; bv[7]=b1.w;
#pragma unroll
        for (int i = 0; i < 8; ++i) {
            float av = __half2float(ah[i]);
#pragma unroll
            for (int j = 0; j < 8; ++j) acc[i][j] = fmaf(av, bv[j], acc[i][j]);
        }
    }

    __half* wp = g_wp + (size_t)b * DIM * DIM;
#pragma unroll
    for (int i = 0; i < 8; ++i) {
        int din = chunk * 256 + ty * 8 + i;
        __half o[8];
#pragma unroll
        for (int j = 0; j < 8; ++j) o[j] = __float2half_rn(acc[i][j]);
        *(uint4*)&wp[(size_t)din * DIM + h * 64 + tx * 8] = *(const uint4*)o;
    }
}

// ---------------- LayerNorm(proj(fp16) + bo + x(f32)), warp-per-row -----------
__global__ __launch_bounds__(256) void ln_kernel(
    const float* __restrict__ x, const float* __restrict__ bo,
    const float* __restrict__ gamma, const float* __restrict__ beta,
    float* __restrict__ out)
{
    int wid = threadIdx.x >> 5;
    int lane = threadIdx.x & 31;
    int row = blockIdx.x * 8 + wid;
    const __half* pr = g_projh + (size_t)row * DIM;
    const float*  xr = x       + (size_t)row * DIM;

    float v[32];
    float s = 0.0f, s2 = 0.0f;
#pragma unroll
    for (int c = 0; c < 8; ++c) {
        int base = c * 128 + lane * 4;
        uint2 pu = *(const uint2*)(pr + base);
        __half2 p0 = *reinterpret_cast<__half2*>(&pu.x);
        __half2 p1 = *reinterpret_cast<__half2*>(&pu.y);
        float4 xv = *(const float4*)(xr + base);
        float4 bv = *(const float4*)(bo + base);
        float* vc = v + c * 4;
        vc[0] = __low2float(p0) + xv.x + bv.x;
        vc[1] = __high2float(p0) + xv.y + bv.y;
        vc[2] = __low2float(p1) + xv.z + bv.z;
        vc[3] = __high2float(p1) + xv.w + bv.w;
#pragma unroll
        for (int k = 0; k < 4; ++k) { s += vc[k]; s2 += vc[k] * vc[k]; }
    }

#pragma unroll
    for (int o = 16; o > 0; o >>= 1) {
        s  += __shfl_xor_sync(0xFFFFFFFFu, s,  o);
        s2 += __shfl_xor_sync(0xFFFFFFFFu, s2, o);
    }
    float mu  = s  * (1.0f / DIM);
    float var = s2 * (1.0f / DIM) - mu * mu;
    float rstd = rsqrtf(var + LNEPS);

#pragma unroll
    for (int c = 0; c < 8; ++c) {
        int base = c * 128 + lane * 4;
        float4 gp = *(const float4*)(gamma + base);
        float4 bp = *(const float4*)(beta  + base);
        float* vc = v + c * 4;
        float4 o4;
        o4.x = (vc[0] - mu) * rstd * gp.x + bp.x;
        o4.y = (vc[1] - mu) * rstd * gp.y + bp.y;
        o4.z = (vc[2] - mu) * rstd * gp.z + bp.z;
        o4.w = (vc[3] - mu) * rstd * gp.w + bp.w;
        *(float4*)(out + (size_t)row * DIM + base) = o4;
    }
}

// ---------------- host launcher ----------------------------------------------
extern "C" void kernel_launch(void* const* d_in, const int* in_sizes, int n_in,
                              void* d_out, int out_size)
{
    (void)in_sizes; (void)n_in; (void)out_size;
    const float* x     = (const float*)d_in[0];
    const float* Wq    = (const float*)d_in[1];
    const float* Wk    = (const float*)d_in[2];
    const float* Wv    = (const float*)d_in[3];
    const float* Wo    = (const float*)d_in[4];
    const float* bo    = (const float*)d_in[5];
    const float* alpha = (const float*)d_in[6];
    const float* temp  = (const float*)d_in[7];
    const float* gamma = (const float*)d_in[8];
    const float* beta  = (const float*)d_in[9];
    float* out = (float*)d_out;

    __half *xh, *wh, *gm, *hk, *wpp, *w2p, *projh;
    cudaGetSymbolAddress((void**)&xh,    g_xh);
    cudaGetSymbolAddress((void**)&wh,    g_wh);
    cudaGetSymbolAddress((void**)&gm,    g_gm);
    cudaGetSymbolAddress((void**)&hk,    g_hk);
    cudaGetSymbolAddress((void**)&wpp,   g_wp);
    cudaGetSymbolAddress((void**)&w2p,   g_w2);
    cudaGetSymbolAddress((void**)&projh, g_projh);

    const int SMEM_GEMM = 98304;
    const int SMEM_WIDE = 147456;
    cudaFuncSetAttribute(gemm_f16,
                         cudaFuncAttributeMaxDynamicSharedMemorySize, SMEM_GEMM);
    cudaFuncSetAttribute(gsplit_kernel,
                         cudaFuncAttributeMaxDynamicSharedMemorySize, SMEM_GEMM);
    cudaFuncSetAttribute(gemm_wide,
                         cudaFuncAttributeMaxDynamicSharedMemorySize, SMEM_WIDE);
    cudaFuncSetAttribute(kkt2_solve_kernel,
                         cudaFuncAttributeMaxDynamicSharedMemorySize, KS_SMEM);

    const size_t WSZ = (size_t)DIM * DIM;

    // fused conversions: x -> xh/xt and 4 weights -> fp16
    conv_all<<<dim3(DIM/64, SEQ/64, BATCH + 1), 256>>>(x, Wq, Wk, Wv, Wo);

    // G_b = X_b^T X_b: split-K=2 f32 partials on triangle, then reduce+mirror
    gsplit_kernel<<<dim3(36, 1, BATCH*2), 256, SMEM_GEMM>>>();
    greduce_kernel<<<dim3(72, 1, BATCH), 256>>>();

    // Hk_b = Wk @ G_b  (wide tile, 1 CTA/SM, 128 CTAs = one wave)
    gemm_wide<<<dim3(DIM/256, DIM/128, BATCH), 256, SMEM_WIDE>>>(
        wh + 1*WSZ, gm, hk, DIM, DIM/64, DIM, DIM, 0, WSZ, WSZ);

    // per-head Gram blocks + solve + softmax (fused)
    kkt2_solve_kernel<<<BH, 512, KS_SMEM>>>(alpha, temp);

    // fold amap into weights
    fold1_kernel<<<dim3(BH, DIM/256), 256>>>();
    gemm_wide<<<dim3(DIM/256, DIM/128, BATCH), 256, SMEM_WIDE>>>(
        wh + 3*WSZ, wpp, w2p, DIM, DIM/64, DIM, DIM, 0, WSZ, WSZ);

    // proj[b] = x[b] @ W2_b  (fp16 out; bias folded into ln)
    gemm_f16<<<dim3(DIM/128, SEQ/128, BATCH), 256, SMEM_GEMM>>>(
        xh, w2p, nullptr, projh, DIM, DIM/64, DIM, DIM,
        (size_t)SEQ*DIM, WSZ, (size_t)SEQ*DIM);

    ln_kernel<<<MTOT/8, 256>>>(x, bo, gamma, beta, out);
}